// round 14
// baseline (speedup 1.0000x reference)
#include <cuda_runtime.h>
#include <cuda_bf16.h>

#define NN 50000
#define NE 600000
#define HID 128
#define NT 256

typedef unsigned long long u64;
typedef unsigned int u32;
typedef unsigned short u16;

// ---------------- scratch ----------------
__device__ float g_h[NN * HID];
__device__ float g_pre[NN * 256];      // [0:64)=u_s, [64:128)=u_d, [128:256)=vh
__device__ float g_msgbuf[(u64)NE * 128];
__device__ float g_sumexp[3 * NN];
__device__ float g_scores[NE];
__device__ float g_es[NE];
__device__ int   g_src[NE];
__device__ int   g_dst[NE];
__device__ unsigned g_maxenc[3];
__device__ int   g_is64;
// CSR by dst
__device__ int g_cnt[NN];
__device__ int g_row[NN];
__device__ int g_cur[NN];
__device__ int g_eord[NE];
// bf16 hi/lo splits
__device__ __align__(16) u16 g_hh[NN * HID];
__device__ __align__(16) u16 g_hl[NN * HID];
__device__ __align__(16) u16 g_eah[NE * 16];
__device__ __align__(16) u16 g_eal[NE * 16];
__device__ __align__(16) u16 g_NPh[3 * 256 * 128];
__device__ __align__(16) u16 g_NPl[3 * 256 * 128];
__device__ __align__(16) u16 g_EWh[3 * 192 * 16];
__device__ __align__(16) u16 g_EWl[3 * 192 * 16];
__device__ __align__(16) u16 g_W2h[3 * 128 * 128];
__device__ __align__(16) u16 g_W2l[3 * 128 * 128];
__device__ __align__(16) u16 g_U1h[3 * 256 * 128];
__device__ __align__(16) u16 g_U1l[3 * 256 * 128];
__device__ __align__(16) u16 g_U2h[3 * 128 * 128];
__device__ __align__(16) u16 g_U2l[3 * 128 * 128];

__device__ __forceinline__ unsigned fenc(float f) {
    unsigned u = __float_as_uint(f);
    return (u & 0x80000000u) ? ~u : (u | 0x80000000u);
}
__device__ __forceinline__ float fdec(unsigned u) {
    return (u & 0x80000000u) ? __uint_as_float(u & 0x7fffffffu)
                             : __uint_as_float(~u);
}

// ---------------- bf16 split helpers ----------------
__device__ __forceinline__ void split_bf16(float v, u16 &h, u16 &l) {
    __nv_bfloat16 bh = __float2bfloat16(v);
    __nv_bfloat16 bl = __float2bfloat16(v - __bfloat162float(bh));
    h = __bfloat16_as_ushort(bh);
    l = __bfloat16_as_ushort(bl);
}
__device__ __forceinline__ void split2(float a, float b, u32 &h, u32 &l) {
    u16 h0, l0, h1, l1;
    split_bf16(a, h0, l0);
    split_bf16(b, h1, l1);
    h = (u32)h0 | ((u32)h1 << 16);
    l = (u32)l0 | ((u32)l1 << 16);
}

// ---------------- HMMA helpers ----------------
__device__ __forceinline__ u32 smem_u32(const void* p) {
    u32 a;
    asm("{ .reg .u64 t; cvta.to.shared.u64 t, %1; cvt.u32.u64 %0, t; }"
        : "=r"(a) : "l"(p));
    return a;
}
__device__ __forceinline__ void ldsm4(u32* r, u32 addr) {
    asm volatile("ldmatrix.sync.aligned.m8n8.x4.shared.b16 {%0,%1,%2,%3}, [%4];"
        : "=r"(r[0]), "=r"(r[1]), "=r"(r[2]), "=r"(r[3]) : "r"(addr));
}
__device__ __forceinline__ void ldsm2(u32* r, u32 addr) {
    asm volatile("ldmatrix.sync.aligned.m8n8.x2.shared.b16 {%0,%1}, [%2];"
        : "=r"(r[0]), "=r"(r[1]) : "r"(addr));
}
__device__ __forceinline__ void mma16816(float* d, const u32* a, const u32* b) {
    asm volatile("mma.sync.aligned.m16n8k16.row.col.f32.bf16.bf16.f32 "
        "{%0,%1,%2,%3}, {%4,%5,%6,%7}, {%8,%9}, {%0,%1,%2,%3};"
        : "+f"(d[0]), "+f"(d[1]), "+f"(d[2]), "+f"(d[3])
        : "r"(a[0]), "r"(a[1]), "r"(a[2]), "r"(a[3]), "r"(b[0]), "r"(b[1]));
}

// ---------------- weight preconversion ----------------
__global__ void k_prep(const float* __restrict__ mw1, const float* __restrict__ mw2,
                       const float* __restrict__ aw1, const float* __restrict__ uw1,
                       const float* __restrict__ uw2) {
    int idx = blockIdx.x * blockDim.x + threadIdx.x;
    const int NP = 3 * 256 * 128, EW = 3 * 192 * 16, W2 = 3 * 128 * 128;
    const int U1 = 3 * 256 * 128, U2 = 3 * 128 * 128;
    u16 h, l;
    if (idx < NP) {
        int lyr = idx / (256 * 128);
        int rem = idx % (256 * 128);
        int n = rem / 128, k = rem % 128;
        float v;
        if (n < 64)        v = aw1[lyr * 64 * 272 + n * 272 + k];
        else if (n < 128)  v = aw1[lyr * 64 * 272 + (n - 64) * 272 + 128 + k];
        else               v = mw1[lyr * 128 * 144 + (n - 128) * 144 + k];
        split_bf16(v, h, l);
        g_NPh[idx] = h; g_NPl[idx] = l;
    } else if (idx < NP + EW) {
        int i = idx - NP;
        int lyr = i / (192 * 16);
        int rem = i % (192 * 16);
        int n = rem / 16, k = rem % 16;
        float v = (n < 64) ? aw1[lyr * 64 * 272 + n * 272 + 256 + k]
                           : mw1[lyr * 128 * 144 + (n - 64) * 144 + 128 + k];
        split_bf16(v, h, l);
        g_EWh[i] = h; g_EWl[i] = l;
    } else if (idx < NP + EW + W2) {
        int i = idx - NP - EW;
        split_bf16(mw2[i], h, l);
        g_W2h[i] = h; g_W2l[i] = l;
    } else if (idx < NP + EW + W2 + U1) {
        int i = idx - NP - EW - W2;
        int lyr = i / 32768;
        int rem = i % 32768;
        int half = rem / 16384;
        int r2 = rem % 16384;
        int n = r2 / 128, k = r2 % 128;
        split_bf16(uw1[lyr * 32768 + n * 256 + half * 128 + k], h, l);
        g_U1h[i] = h; g_U1l[i] = l;
    } else if (idx < NP + EW + W2 + U1 + U2) {
        int i = idx - NP - EW - W2 - U1;
        split_bf16(uw2[i], h, l);
        g_U2h[i] = h; g_U2l[i] = l;
    }
}

// ---------------- detect + convert + ea split + zero ----------------
__global__ void k_detect(const unsigned* __restrict__ raw) {
    __shared__ int nz;
    if (threadIdx.x == 0) nz = 0;
    __syncthreads();
    for (int i = threadIdx.x; i < 2048; i += NT)
        if (raw[2 * i + 1] != 0u) atomicOr(&nz, 1);
    __syncthreads();
    if (threadIdx.x == 0) g_is64 = (nz == 0) ? 1 : 0;
}

__global__ void k_convert(const void* __restrict__ eidx, const float* __restrict__ ea) {
    int i = blockIdx.x * blockDim.x + threadIdx.x;
    long long stride = (long long)gridDim.x * blockDim.x;
    if (i < NE) {
        if (g_is64) {
            const long long* p = (const long long*)eidx;
            g_src[i] = (int)p[i];
            g_dst[i] = (int)p[NE + i];
        } else {
            const int* p = (const int*)eidx;
            g_src[i] = p[i];
            g_dst[i] = p[NE + i];
        }
    }
    for (long long j = i; j < (long long)NE * 16; j += stride) {
        u16 h, l;
        split_bf16(ea[j], h, l);
        g_eah[j] = h; g_eal[j] = l;
    }
    for (long long j = i; j < 3 * NN; j += stride) g_sumexp[j] = 0.f;
    for (long long j = i; j < NN; j += stride) g_cnt[j] = 0;
    if (i == 0) {
        g_maxenc[0] = 0x007FFFFFu;
        g_maxenc[1] = 0x007FFFFFu;
        g_maxenc[2] = 0x007FFFFFu;
    }
}

// ---------------- counting sort by dst (CSR) ----------------
__global__ void k_hist() {
    int i = blockIdx.x * blockDim.x + threadIdx.x;
    if (i < NE) atomicAdd(&g_cnt[g_dst[i]], 1);
}

__global__ void k_scan() {
    __shared__ int warpsum[32];
    __shared__ int scarry;
    int tid = threadIdx.x, lane = tid & 31, wid = tid >> 5;
    if (tid == 0) scarry = 0;
    __syncthreads();
    for (int base = 0; base < NN; base += 1024) {
        int i = base + tid;
        int v = (i < NN) ? g_cnt[i] : 0;
        int s = v;
#pragma unroll
        for (int off = 1; off < 32; off <<= 1) {
            int t = __shfl_up_sync(0xffffffffu, s, off);
            if (lane >= off) s += t;
        }
        if (lane == 31) warpsum[wid] = s;
        __syncthreads();
        if (wid == 0) {
            int ws = warpsum[lane];
#pragma unroll
            for (int off = 1; off < 32; off <<= 1) {
                int t = __shfl_up_sync(0xffffffffu, ws, off);
                if (lane >= off) ws += t;
            }
            warpsum[lane] = ws;
        }
        __syncthreads();
        int incl = s + (wid > 0 ? warpsum[wid - 1] : 0) + scarry;
        if (i < NN) { g_row[i] = incl - v; g_cur[i] = incl - v; }
        __syncthreads();
        if (tid == 1023) scarry = incl;
        __syncthreads();
    }
}

__global__ void k_scatter() {
    int i = blockIdx.x * blockDim.x + threadIdx.x;
    if (i < NE) {
        int pos = atomicAdd(&g_cur[g_dst[i]], 1);
        g_eord[pos] = i;
    }
}

// ---------------- node projection (+ split store) ----------------
__global__ void k_nodeproj(const float* __restrict__ x,
                           const float* __restrict__ W,
                           const float* __restrict__ b) {
    __shared__ float sA[32 * 33];
    __shared__ float sW[128 * 33];
    int tid = threadIdx.x;
    int n0 = blockIdx.x * 32;
    for (int idx = tid; idx < 32 * 32; idx += NT) {
        int r = idx >> 5, k = idx & 31;
        int n = n0 + r;
        sA[r * 33 + k] = (n < NN) ? x[n * 32 + k] : 0.f;
    }
    for (int idx = tid; idx < 128 * 32; idx += NT) {
        int o = idx >> 5, k = idx & 31;
        sW[o * 33 + k] = W[o * 32 + k];
    }
    __syncthreads();
    int tc = tid & 31, trg = tid >> 5;
    float acc[4][4] = {};
#pragma unroll 8
    for (int k = 0; k < 32; k++) {
        float a[4], w[4];
#pragma unroll
        for (int i = 0; i < 4; i++) a[i] = sA[(trg * 4 + i) * 33 + k];
#pragma unroll
        for (int j = 0; j < 4; j++) w[j] = sW[(tc + 32 * j) * 33 + k];
#pragma unroll
        for (int i = 0; i < 4; i++)
#pragma unroll
            for (int j = 0; j < 4; j++) acc[i][j] += a[i] * w[j];
    }
#pragma unroll
    for (int i = 0; i < 4; i++) {
        int n = n0 + trg * 4 + i;
        if (n < NN)
#pragma unroll
            for (int j = 0; j < 4; j++) {
                int c = tc + 32 * j;
                float v = fmaxf(acc[i][j] + b[c], 0.f);
                g_h[n * HID + c] = v;
                u16 h, l;
                split_bf16(v, h, l);
                g_hh[n * HID + c] = h;
                g_hl[n * HID + c] = l;
            }
    }
}

// ---------------- node precompute GEMM: M=64 tiles, 2 CTAs/SM (layer 0 only) ----------------
#define NPP 136
#define NP_AH 0
#define NP_AL 17408
#define NP_WH 34816
#define NP_WL 69632
#define SMEM_NP 104448

__global__ void __launch_bounds__(256, 2)
k_node_pre(int layer) {
    extern __shared__ char sm[];
    u16* sAh = (u16*)(sm + NP_AH);
    u16* sAl = (u16*)(sm + NP_AL);
    u16* sWh = (u16*)(sm + NP_WH);
    u16* sWl = (u16*)(sm + NP_WL);
    u32 sb = smem_u32(sm);
    int tid = threadIdx.x, lane = tid & 31, w = tid >> 5;
    int n0 = blockIdx.x * 64;

    for (int idx = tid; idx < 64 * 16; idx += 256) {
        int r = idx >> 4, c = (idx & 15) * 8;
        int n = n0 + r;
        if (n < NN) {
            *(uint4*)&sAh[r * NPP + c] = *(const uint4*)&g_hh[n * HID + c];
            *(uint4*)&sAl[r * NPP + c] = *(const uint4*)&g_hl[n * HID + c];
        } else {
            uint4 z = make_uint4(0, 0, 0, 0);
            *(uint4*)&sAh[r * NPP + c] = z;
            *(uint4*)&sAl[r * NPP + c] = z;
        }
    }

    int m0 = (w & 1) * 32, n0w = (w >> 1) * 32;
    for (int half = 0; half < 2; half++) {
        const u16* wh = g_NPh + layer * 256 * 128 + half * 128 * 128;
        const u16* wl = g_NPl + layer * 256 * 128 + half * 128 * 128;
        for (int idx = tid; idx < 128 * 16; idx += 256) {
            int r = idx >> 4, c = (idx & 15) * 8;
            *(uint4*)&sWh[r * NPP + c] = *(const uint4*)&wh[r * 128 + c];
            *(uint4*)&sWl[r * NPP + c] = *(const uint4*)&wl[r * 128 + c];
        }
        __syncthreads();
        float acc[2][4][4];
#pragma unroll
        for (int i = 0; i < 2; i++)
#pragma unroll
            for (int j = 0; j < 4; j++)
#pragma unroll
                for (int k = 0; k < 4; k++) acc[i][j][k] = 0.f;
        for (int ks = 0; ks < 8; ks++) {
            int kb = ks * 16;
            u32 ah[2][4], al[2][4];
#pragma unroll
            for (int mt = 0; mt < 2; mt++) {
                int r = m0 + mt * 16 + (lane & 15);
                int c = kb + ((lane >> 4) << 3);
                u32 off = (u32)(r * NPP + c) * 2;
                ldsm4(ah[mt], sb + NP_AH + off);
                ldsm4(al[mt], sb + NP_AL + off);
            }
#pragma unroll
            for (int nt = 0; nt < 4; nt++) {
                int rn = n0w + nt * 8 + (lane & 7);
                int cn = kb + (((lane >> 3) & 1) << 3);
                u32 offb = (u32)(rn * NPP + cn) * 2;
                u32 bh[2], bl[2];
                ldsm2(bh, sb + NP_WH + offb);
                ldsm2(bl, sb + NP_WL + offb);
#pragma unroll
                for (int mt = 0; mt < 2; mt++) {
                    mma16816(acc[mt][nt], ah[mt], bh);
                    mma16816(acc[mt][nt], ah[mt], bl);
                    mma16816(acc[mt][nt], al[mt], bh);
                }
            }
        }
#pragma unroll
        for (int mt = 0; mt < 2; mt++)
#pragma unroll
            for (int nt = 0; nt < 4; nt++) {
                int rA = m0 + mt * 16 + (lane >> 2);
                int rB = rA + 8;
                int c = half * 128 + n0w + nt * 8 + 2 * (lane & 3);
                int nA = n0 + rA, nB = n0 + rB;
                if (nA < NN) {
                    g_pre[(u64)nA * 256 + c]     = acc[mt][nt][0];
                    g_pre[(u64)nA * 256 + c + 1] = acc[mt][nt][1];
                }
                if (nB < NN) {
                    g_pre[(u64)nB * 256 + c]     = acc[mt][nt][2];
                    g_pre[(u64)nB * 256 + c + 1] = acc[mt][nt][3];
                }
            }
        __syncthreads();
    }
}

// ---------------- attention scores (elementwise, decomposed) ----------------
__global__ void __launch_bounds__(256, 4)
k_attn_lite(const float* __restrict__ ea,
            const float* __restrict__ aw1l,
            const float* __restrict__ ab1,
            const float* __restrict__ aw2,
            const float* __restrict__ ab2p, int layer) {
    __shared__ float sea[64 * 17];
    __shared__ float sW[64 * 16];
    __shared__ float sb1[64], sv[64];
    __shared__ unsigned smax;
    int tid = threadIdx.x;
    int e0 = blockIdx.x * 64;
    if (tid == 0) smax = 0x007FFFFFu;
    {
        int r = tid >> 2, c = (tid & 3) * 4;
        float4 v = make_float4(0.f, 0.f, 0.f, 0.f);
        if (e0 + r < NE) v = *(const float4*)&ea[(u64)(e0 + r) * 16 + c];
        sea[r * 17 + c]     = v.x;
        sea[r * 17 + c + 1] = v.y;
        sea[r * 17 + c + 2] = v.z;
        sea[r * 17 + c + 3] = v.w;
    }
    {
        int r = tid >> 2, c = (tid & 3) * 4;
        float4 wv = *(const float4*)&aw1l[r * 272 + 256 + c];
        *(float4*)&sW[r * 16 + c] = wv;
    }
    if (tid < 64) { sb1[tid] = ab1[tid]; sv[tid] = aw2[tid]; }
    __syncthreads();

    int el = tid >> 2, p = tid & 3;
    int e = e0 + el;
    float score = 0.f;
    if (e < NE) {
        int s = g_src[e], d = g_dst[e];
        const float* ps = &g_pre[(u64)s * 256 + p * 16];
        const float* pd = &g_pre[(u64)d * 256 + 64 + p * 16];
        const float* er = &sea[el * 17];
#pragma unroll
        for (int c4 = 0; c4 < 4; c4++) {
            float4 a4 = *(const float4*)&ps[c4 * 4];
            float4 b4 = *(const float4*)&pd[c4 * 4];
            float av[4] = {a4.x, a4.y, a4.z, a4.w};
            float bv[4] = {b4.x, b4.y, b4.z, b4.w};
#pragma unroll
            for (int j = 0; j < 4; j++) {
                int c = p * 16 + c4 * 4 + j;
                float x = av[j] + bv[j] + sb1[c];
                const float* wr = &sW[c * 16];
#pragma unroll
                for (int k = 0; k < 16; k++) x += er[k] * wr[k];
                x = (x > 0.f) ? x : 0.2f * x;
                score += x * sv[c];
            }
        }
    }
    score += __shfl_xor_sync(0xffffffffu, score, 1);
    score += __shfl_xor_sync(0xffffffffu, score, 2);
    if (p == 0 && e < NE) {
        float sc = score + ab2p[0];
        g_scores[e] = sc;
        atomicMax(&smax, fenc(sc));
    }
    __syncthreads();
    if (tid == 0) atomicMax(&g_maxenc[layer], smax);
}

// ---------------- exp + scatter sum ----------------
__global__ void k_exp(int layer) {
    int i = blockIdx.x * blockDim.x + threadIdx.x;
    if (i >= NE) return;
    float m = fdec(g_maxenc[layer]);
    float es = expf(g_scores[i] - m);
    g_es[i] = es;
    atomicAdd(&g_sumexp[layer * NN + g_dst[i]], es);
}

// ---------------- message MLP: persistent, split-N, 3 CTAs/SM ----------------
#define AP2 136
#define M_AH 0
#define M_AL 17408
#define M_WH 34816
#define M_WL 52224
#define M_META 69632
#define SMEM_MSG2 (69632 + 1536)
#define NTILES ((NE + 63) / 64)
#define MSG_GRID 444
#define MSG_SLOTS (MSG_GRID / 2)

__global__ void __launch_bounds__(256, 3)
k_msg(const float* __restrict__ mb1,
      const float* __restrict__ mb2, int layer) {
    extern __shared__ char sm[];
    u16* sAh = (u16*)(sm + M_AH);   // 64 x 136
    u16* sAl = (u16*)(sm + M_AL);
    u16* sWh = (u16*)(sm + M_WH);   // 64 x 136 (W2 column-half)
    u16* sWl = (u16*)(sm + M_WL);
    int*   ssrc = (int*)(sm + M_META);
    float* swt  = (float*)(sm + M_META + 256);
    float* smb1 = (float*)(sm + M_META + 512);
    float* smb2 = (float*)(sm + M_META + 1024);
    u32 sb = smem_u32(sm);

    int tid = threadIdx.x, lane = tid & 31, w = tid >> 5;
    int cg = blockIdx.x & 1;          // output column group (0: cols 0..63, 1: 64..127)
    int slot = blockIdx.x >> 1;
    int ncol0 = cg * 64;
    int m0 = (w & 1) * 32;
    int n0 = (w >> 1) * 32;           // GEMM_ea / epilogue-ea over full 128 cols
    int n0h = (w >> 1) * 16;          // GEMM2 over 64 local cols

    // ---- one-time setup: stage Wea (full 128 rows) in A area, load W2 half, biases ----
    {
        const u16* wh = g_EWh + layer * 192 * 16 + 64 * 16;
        const u16* wl = g_EWl + layer * 192 * 16 + 64 * 16;
        for (int idx = tid; idx < 128 * 2; idx += 256) {
            int r = idx >> 1, c = (idx & 1) * 8;
            *(uint4*)&sAh[r * 16 + c] = *(const uint4*)&wh[r * 16 + c];
            *(uint4*)&sAl[r * 16 + c] = *(const uint4*)&wl[r * 16 + c];
        }
        const u16* w2h = g_W2h + layer * 128 * 128;
        const u16* w2l = g_W2l + layer * 128 * 128;
        for (int idx = tid; idx < 64 * 16; idx += 256) {
            int r = idx >> 4, c = (idx & 15) * 8;
            *(uint4*)&sWh[r * AP2 + c] = *(const uint4*)&w2h[(ncol0 + r) * 128 + c];
            *(uint4*)&sWl[r * AP2 + c] = *(const uint4*)&w2l[(ncol0 + r) * 128 + c];
        }
        if (tid < 128) { smb1[tid] = mb1[tid]; smb2[tid] = mb2[tid]; }
    }
    __syncthreads();
    // Wea fragments -> registers (held across all tiles; full 128 output cols)
    u32 weah[4][2], weal[4][2];
#pragma unroll
    for (int nt = 0; nt < 4; nt++) {
        int rn = n0 + nt * 8 + (lane & 7);
        int cn = ((lane >> 3) & 1) << 3;
        u32 off = (u32)(rn * 16 + cn) * 2;
        ldsm2(weah[nt], sb + M_AH + off);
        ldsm2(weal[nt], sb + M_AL + off);
    }
    __syncthreads();

    for (int t = slot; t < NTILES; t += MSG_SLOTS) {
        int e0 = t * 64;
        if (tid < 64) {
            int e = e0 + tid;
            if (e < NE) {
                ssrc[tid] = g_src[e];
                int d = g_dst[e];
                swt[tid] = g_es[e] / (g_sumexp[layer * NN + d] + 1e-6f);
            } else {
                ssrc[tid] = 0; swt[tid] = 0.f;
            }
        }
        // ea split -> A tile cols 0..15
        for (int idx = tid; idx < 64 * 2; idx += 256) {
            int r = idx >> 1, c = (idx & 1) * 8;
            int e = min(e0 + r, NE - 1);
            *(uint4*)&sAh[r * AP2 + c] = *(const uint4*)&g_eah[(u64)e * 16 + c];
            *(uint4*)&sAl[r * AP2 + c] = *(const uint4*)&g_eal[(u64)e * 16 + c];
        }
        __syncthreads();

        // GEMM_ea: K=16, full 128 output cols (Wea from registers)
        float acc[2][4][4];
#pragma unroll
        for (int i = 0; i < 2; i++)
#pragma unroll
            for (int j = 0; j < 4; j++)
#pragma unroll
                for (int k = 0; k < 4; k++) acc[i][j][k] = 0.f;
        {
            u32 ah[2][4], al[2][4];
#pragma unroll
            for (int mt = 0; mt < 2; mt++) {
                int r = m0 + mt * 16 + (lane & 15);
                int c = (lane >> 4) << 3;
                u32 off = (u32)(r * AP2 + c) * 2;
                ldsm4(ah[mt], sb + M_AH + off);
                ldsm4(al[mt], sb + M_AL + off);
            }
#pragma unroll
            for (int nt = 0; nt < 4; nt++) {
#pragma unroll
                for (int mt = 0; mt < 2; mt++) {
                    mma16816(acc[mt][nt], ah[mt], weah[nt]);
                    mma16816(acc[mt][nt], ah[mt], weal[nt]);
                    mma16816(acc[mt][nt], al[mt], weah[nt]);
                }
            }
        }
        __syncthreads();

        // epilogue-ea: m = relu(eaW + vh + b1) -> split into A tiles (full 128 cols)
#pragma unroll
        for (int mt = 0; mt < 2; mt++)
#pragma unroll
            for (int nt = 0; nt < 4; nt++) {
                int rA = m0 + mt * 16 + (lane >> 2);
                int rB = rA + 8;
                int c = n0 + nt * 8 + 2 * (lane & 3);
                float b0 = smb1[c], b1 = smb1[c + 1];
                float2 vA = *(const float2*)&g_pre[(u64)ssrc[rA] * 256 + 128 + c];
                float2 vB = *(const float2*)&g_pre[(u64)ssrc[rB] * 256 + 128 + c];
                u32 h, l;
                split2(fmaxf(acc[mt][nt][0] + vA.x + b0, 0.f),
                       fmaxf(acc[mt][nt][1] + vA.y + b1, 0.f), h, l);
                *(u32*)&sAh[rA * AP2 + c] = h;
                *(u32*)&sAl[rA * AP2 + c] = l;
                split2(fmaxf(acc[mt][nt][2] + vB.x + b0, 0.f),
                       fmaxf(acc[mt][nt][3] + vB.y + b1, 0.f), h, l);
                *(u32*)&sAh[rB * AP2 + c] = h;
                *(u32*)&sAl[rB * AP2 + c] = l;
            }
        __syncthreads();

        // GEMM2 K=128 -> 64 local output cols (W2 half resident)
        float acc2[2][2][4];
#pragma unroll
        for (int i = 0; i < 2; i++)
#pragma unroll
            for (int j = 0; j < 2; j++)
#pragma unroll
                for (int k = 0; k < 4; k++) acc2[i][j][k] = 0.f;

        for (int ks = 0; ks < 8; ks++) {
            int kb = ks * 16;
            u32 ah[2][4], al[2][4];
#pragma unroll
            for (int mt = 0; mt < 2; mt++) {
                int r = m0 + mt * 16 + (lane & 15);
                int c = kb + ((lane >> 4) << 3);
                u32 off = (u32)(r * AP2 + c) * 2;
                ldsm4(ah[mt], sb + M_AH + off);
                ldsm4(al[mt], sb + M_AL + off);
            }
#pragma unroll
            for (int nt = 0; nt < 2; nt++) {
                int rn = n0h + nt * 8 + (lane & 7);
                int cn = kb + (((lane >> 3) & 1) << 3);
                u32 offb = (u32)(rn * AP2 + cn) * 2;
                u32 bh[2], bl[2];
                ldsm2(bh, sb + M_WH + offb);
                ldsm2(bl, sb + M_WL + offb);
#pragma unroll
                for (int mt = 0; mt < 2; mt++) {
                    mma16816(acc2[mt][nt], ah[mt], bh);
                    mma16816(acc2[mt][nt], ah[mt], bl);
                    mma16816(acc2[mt][nt], al[mt], bh);
                }
            }
        }

        // epilogue2: weighted message -> coalesced store to msgbuf (col half)
#pragma unroll
        for (int mt = 0; mt < 2; mt++)
#pragma unroll
            for (int nt = 0; nt < 2; nt++) {
                int rA = m0 + mt * 16 + (lane >> 2);
                int rB = rA + 8;
                int gc_ = ncol0 + n0h + nt * 8 + 2 * (lane & 3);
                float b0 = smb2[gc_], b1 = smb2[gc_ + 1];
                float wA = swt[rA], wB = swt[rB];
                int eA = e0 + rA, eB = e0 + rB;
                if (eA < NE) {
                    float2 v;
                    v.x = (acc2[mt][nt][0] + b0) * wA;
                    v.y = (acc2[mt][nt][1] + b1) * wA;
                    *(float2*)&g_msgbuf[(u64)eA * 128 + gc_] = v;
                }
                if (eB < NE) {
                    float2 v;
                    v.x = (acc2[mt][nt][2] + b0) * wB;
                    v.y = (acc2[mt][nt][3] + b1) * wB;
                    *(float2*)&g_msgbuf[(u64)eB * 128 + gc_] = v;
                }
            }
        __syncthreads();
    }
}

// ---------------- node update: CSR gather + HMMA MLP + LN + fused pre ----------------
#define UPP 136
#define U_AH 0
#define U_AL 17408
#define U_WH 34816
#define U_WL 69632
#define SMEM_UPD 104448

__global__ void __launch_bounds__(256, 2)
k_update(const float* __restrict__ ub1,
         const float* __restrict__ ub2,
         const float* __restrict__ lng,
         const float* __restrict__ lnb, int layer, int do_pre) {
    extern __shared__ char sm[];
    u16* sAh = (u16*)(sm + U_AH);
    u16* sAl = (u16*)(sm + U_AL);
    u16* sWh = (u16*)(sm + U_WH);
    u16* sWl = (u16*)(sm + U_WL);
    float* stage = (float*)(sm + U_WH);
    u32 sb = smem_u32(sm);
    int tid = threadIdx.x, lane = tid & 31, w = tid >> 5;
    int n0 = blockIdx.x * 64;

    // phase 0: CSR gather of weighted messages (agg in registers)
    int ln = tid >> 2, q = tid & 3;
    int nn = n0 + ln;
    float agg[32];
#pragma unroll
    for (int t = 0; t < 32; t++) agg[t] = 0.f;
    if (nn < NN) {
        int j0 = g_row[nn], j1 = g_cur[nn];
        for (int j = j0; j < j1; j++) {
            int e = g_eord[j];
            const float* mp = &g_msgbuf[(u64)e * 128 + q * 32];
#pragma unroll
            for (int t = 0; t < 8; t++) {
                float4 v = *(const float4*)&mp[t * 4];
                agg[t * 4]     += v.x;
                agg[t * 4 + 1] += v.y;
                agg[t * 4 + 2] += v.z;
                agg[t * 4 + 3] += v.w;
            }
        }
    }

    // A1 = h split
    for (int idx = tid; idx < 64 * 16; idx += 256) {
        int r = idx >> 4, c = (idx & 15) * 8;
        int n = n0 + r;
        if (n < NN) {
            *(uint4*)&sAh[r * UPP + c] = *(const uint4*)&g_hh[n * HID + c];
            *(uint4*)&sAl[r * UPP + c] = *(const uint4*)&g_hl[n * HID + c];
        } else {
            uint4 z = make_uint4(0, 0, 0, 0);
            *(uint4*)&sAh[r * UPP + c] = z;
            *(uint4*)&sAl[r * UPP + c] = z;
        }
    }
    // Wa (uw1 in-half 0)
    {
        const u16* wh = g_U1h + layer * 32768;
        const u16* wl = g_U1l + layer * 32768;
        for (int idx = tid; idx < 128 * 16; idx += 256) {
            int r = idx >> 4, c = (idx & 15) * 8;
            *(uint4*)&sWh[r * UPP + c] = *(const uint4*)&wh[r * 128 + c];
            *(uint4*)&sWl[r * UPP + c] = *(const uint4*)&wl[r * 128 + c];
        }
    }
    __syncthreads();

    int m0 = (w & 1) * 32, nw0 = (w >> 1) * 32;
    float acc[2][4][4];
#pragma unroll
    for (int i = 0; i < 2; i++)
#pragma unroll
        for (int j = 0; j < 4; j++)
#pragma unroll
            for (int k = 0; k < 4; k++) acc[i][j][k] = 0.f;

    for (int ks = 0; ks < 8; ks++) {
        int kb = ks * 16;
        u32 ah[2][4], al[2][4];
#pragma unroll
        for (int mt = 0; mt < 2; mt++) {
            int r = m0 + mt * 16 + (lane & 15);
            int c = kb + ((lane >> 4) << 3);
            u32 off = (u32)(r * UPP + c) * 2;
            ldsm4(ah[mt], sb + U_AH + off);
            ldsm4(al[mt], sb + U_AL + off);
        }
#pragma unroll
        for (int nt = 0; nt < 4; nt++) {
            int rn = nw0 + nt * 8 + (lane & 7);
            int cn = kb + (((lane >> 3) & 1) << 3);
            u32 offb = (u32)(rn * UPP + cn) * 2;
            u32 bh[2], bl[2];
            ldsm2(bh, sb + U_WH + offb);
            ldsm2(bl, sb + U_WL + offb);
#pragma unroll
            for (int mt = 0; mt < 2; mt++) {
                mma16816(acc[mt][nt], ah[mt], bh);
                mma16816(acc[mt][nt], ah[mt], bl);
                mma16816(acc[mt][nt], al[mt], bh);
            }
        }
    }
    __syncthreads();

    // A2 = agg split; Wb (uw1 in-half 1)
    {
#pragma unroll
        for (int t = 0; t < 16; t++) {
            u32 h, l;
            split2(agg[2 * t], agg[2 * t + 1], h, l);
            *(u32*)&sAh[ln * UPP + q * 32 + 2 * t] = h;
            *(u32*)&sAl[ln * UPP + q * 32 + 2 * t] = l;
        }
        const u16* wh = g_U1h + layer * 32768 + 16384;
        const u16* wl = g_U1l + layer * 32768 + 16384;
        for (int idx = tid; idx < 128 * 16; idx += 256) {
            int r = idx >> 4, c = (idx & 15) * 8;
            *(uint4*)&sWh[r * UPP + c] = *(const uint4*)&wh[r * 128 + c];
            *(uint4*)&sWl[r * UPP + c] = *(const uint4*)&wl[r * 128 + c];
        }
    }
    __syncthreads();

    for (int ks = 0; ks < 8; ks++) {
        int kb = ks * 16;
        u32 ah[2][4], al[2][4];
#pragma unroll
        for (int mt = 0; mt < 2; mt++) {
            int r = m0 + mt * 16 + (lane & 15);
            int c = kb + ((lane >> 4) << 3);
            u32 off = (u32)(r * UPP + c) * 2;
            ldsm4(ah[mt], sb + U_AH + off);
            ldsm4(al[mt], sb + U_AL + off);
        }
#pragma unroll
        for (int nt = 0; nt < 4; nt++) {
            int rn = nw0 + nt * 8 + (lane & 7);
            int cn = kb + (((lane >> 3) & 1) << 3);
            u32 offb = (u32)(rn * UPP + cn) * 2;
            u32 bh[2], bl[2];
            ldsm2(bh, sb + U_WH + offb);
            ldsm2(bl, sb + U_WL + offb);
#pragma unroll
            for (int mt = 0; mt < 2; mt++) {
                mma16816(acc[mt][nt], ah[mt], bh);
                mma16816(acc[mt][nt], ah[mt], bl);
                mma16816(acc[mt][nt], al[mt], bh);
            }
        }
    }
    __syncthreads();

    // relu(acc + ub1) -> re-split into A tiles
#pragma unroll
    for (int mt = 0; mt < 2; mt++)
#pragma unroll
        for (int nt = 0; nt < 4; nt++) {
            int rA = m0 + mt * 16 + (lane >> 2);
            int rB = rA + 8;
            int c = nw0 + nt * 8 + 2 * (lane & 3);
            float b0 = ub1[c], b1 = ub1[c + 1];
            u32 h, l;
            split2(fmaxf(acc[mt][nt][0] + b0, 0.f),
                   fmaxf(acc[mt][nt][1] + b1, 0.f), h, l);
            *(u32*)&sAh[rA * UPP + c] = h;
            *(u32*)&sAl[rA * UPP + c] = l;
            split2(fmaxf(acc[mt][nt][2] + b0, 0.f),
                   fmaxf(acc[mt][nt][3] + b1, 0.f), h, l);
            *(u32*)&sAh[rB * UPP + c] = h;
            *(u32*)&sAl[rB * UPP + c] = l;
        }
    // W2 = uw2 split
    {
        const u16* wh = g_U2h + layer * 128 * 128;
        const u16* wl = g_U2l + layer * 128 * 128;
        for (int idx = tid; idx < 128 * 16; idx += 256) {
            int r = idx >> 4, c = (idx & 15) * 8;
            *(uint4*)&sWh[r * UPP + c] = *(const uint4*)&wh[r * 128 + c];
            *(uint4*)&sWl[r * UPP + c] = *(const uint4*)&wl[r * 128 + c];
        }
    }
    __syncthreads();

    float acc2[2][4][4];
#pragma unroll
    for (int i = 0; i < 2; i++)
#pragma unroll
        for (int j = 0; j < 4; j++)
#pragma unroll
            for (int k = 0; k < 4; k++) acc2[i][j][k] = 0.f;

    for (int ks = 0; ks < 8; ks++) {
        int kb = ks * 16;
        u32 ah[2][4], al[2][4];
#pragma unroll
        for (int mt = 0; mt < 2; mt++) {
            int r = m0 + mt * 16 + (lane & 15);
            int c = kb + ((lane >> 4) << 3);
            u32 off = (u32)(r * UPP + c) * 2;
            ldsm4(ah[mt], sb + U_AH + off);
            ldsm4(al[mt], sb + U_AL + off);
        }
#pragma unroll
        for (int nt = 0; nt < 4; nt++) {
            int rn = nw0 + nt * 8 + (lane & 7);
            int cn = kb + (((lane >> 3) & 1) << 3);
            u32 offb = (u32)(rn * UPP + cn) * 2;
            u32 bh[2], bl[2];
            ldsm2(bh, sb + U_WH + offb);
            ldsm2(bl, sb + U_WL + offb);
#pragma unroll
            for (int mt = 0; mt < 2; mt++) {
                mma16816(acc2[mt][nt], ah[mt], bh);
                mma16816(acc2[mt][nt], ah[mt], bl);
                mma16816(acc2[mt][nt], al[mt], bh);
            }
        }
    }
    __syncthreads();  // W tiles dead -> stage

#pragma unroll
    for (int mt = 0; mt < 2; mt++)
#pragma unroll
        for (int nt = 0; nt < 4; nt++) {
            int rA = m0 + mt * 16 + (lane >> 2);
            int rB = rA + 8;
            int c = nw0 + nt * 8 + 2 * (lane & 3);
            stage[rA * 132 + c]     = acc2[mt][nt][0];
            stage[rA * 132 + c + 1] = acc2[mt][nt][1];
            stage[rB * 132 + c]     = acc2[mt][nt][2];
            stage[rB * 132 + c + 1] = acc2[mt][nt][3];
        }
    __syncthreads();

    // LN: 4 threads per row (ln, q); also deposit split h into A tiles for fused pre
    {
        int c0 = q * 32;
        float v[32];
        float s = 0.f, sq = 0.f;
        if (nn < NN) {
#pragma unroll
            for (int t4 = 0; t4 < 8; t4++) {
                float4 hres = *(const float4*)&g_h[nn * HID + c0 + t4 * 4];
                float hr[4] = {hres.x, hres.y, hres.z, hres.w};
#pragma unroll
                for (int j = 0; j < 4; j++) {
                    int t = t4 * 4 + j;
                    float val = stage[ln * 132 + c0 + t] + ub2[c0 + t] + hr[j];
                    val = fmaxf(val, 0.f);
                    v[t] = val;
                    s += val;
                    sq += val * val;
                }
            }
        } else {
#pragma unroll
            for (int t = 0; t < 32; t++) v[t] = 0.f;
        }
        s  += __shfl_xor_sync(0xffffffffu, s, 1);
        s  += __shfl_xor_sync(0xffffffffu, s, 2);
        sq += __shfl_xor_sync(0xffffffffu, sq, 1);
        sq += __shfl_xor_sync(0xffffffffu, sq, 2);
        float mu = s * (1.f / 128.f);
        float var = sq * (1.f / 128.f) - mu * mu;
        float rs = rsqrtf(var + 1e-5f);
        float o[32];
#pragma unroll
        for (int t = 0; t < 32; t++)
            o[t] = (v[t] - mu) * rs * lng[c0 + t] + lnb[c0 + t];
        if (nn < NN) {
#pragma unroll
            for (int t4 = 0; t4 < 8; t4++) {
                *(float4*)&g_h[nn * HID + c0 + t4 * 4] =
                    make_float4(o[t4 * 4], o[t4 * 4 + 1], o[t4 * 4 + 2], o[t4 * 4 + 3]);
                u32 h0, l0, h1, l1;
                split2(o[t4 * 4], o[t4 * 4 + 1], h0, l0);
                split2(o[t4 * 4 + 2], o[t4 * 4 + 3], h1, l1);
                *(u32*)&g_hh[nn * HID + c0 + t4 * 4]     = h0;
                *(u32*)&g_hh[nn * HID + c0 + t4 * 4 + 2] = h1;
                *(u32*)&g_hl[nn * HID + c0 + t4 * 4]     = l0;
                *(u32*)&g_hl[nn * HID + c0 + t4 * 4 + 2] = l1;
            }
        }
        if (do_pre) {
#pragma unroll
            for (int t = 0; t < 16; t++) {
                u32 h, l;
                split2(o[2 * t], o[2 * t + 1], h, l);
                *(u32*)&sAh[ln * UPP + c0 + 2 * t] = h;
                *(u32*)&sAl[ln * UPP + c0 + 2 * t] = l;
            }
        }
    }

    // ---- fused next-layer node_pre ----
    if (do_pre) {
        __syncthreads();
        int npl = layer + 1;
        for (int half = 0; half < 2; half++) {
            const u16* wh = g_NPh + npl * 256 * 128 + half * 128 * 128;
            const u16* wl = g_NPl + npl * 256 * 128 + half * 128 * 128;
            for (int idx = tid; idx < 128 * 16; idx += 256) {
                int r = idx >> 4, c = (idx & 15) * 8;
                *(uint4*)&sWh[r * UPP + c] = *(const uint4*)&wh[r * 128 + c];
                *(uint4*)&sWl[r * UPP + c] = *(const uint4*)&wl[r * 128 + c];
            }
            __syncthreads();
            float accp[2][4][4];
#pragma unroll
            for (int i = 0; i < 2; i++)
#pragma unroll
                for (int j = 0; j < 4; j++)
#pragma unroll
                    for (int k = 0; k < 4; k++) accp[i][j][k] = 0.f;
            for (int ks = 0; ks < 8; ks++) {
                int kb = ks * 16;
                u32 ah[2][4], al[2][4];
#pragma unroll
                for (int mt = 0; mt < 2; mt++) {
                    int r = m0 + mt * 16 + (lane & 15);
                    int c = kb + ((lane >> 4) << 3);
                    u32 off = (u32)(r * UPP + c) * 2;
                    ldsm4(ah[mt], sb + U_AH + off);
                    ldsm4(al[mt], sb + U_AL + off);
                }
#pragma unroll
                for (int nt = 0; nt < 4; nt++) {
                    int rn = nw0 + nt * 8 + (lane & 7);
                    int cn = kb + (((lane >> 3) & 1) << 3);
                    u32 offb = (u32)(rn * UPP + cn) * 2;
                    u32 bh[2], bl[2];
                    ldsm2(bh, sb + U_WH + offb);
                    ldsm2(bl, sb + U_WL + offb);
#pragma unroll
                    for (int mt = 0; mt < 2; mt++) {
                        mma16816(accp[mt][nt], ah[mt], bh);
                        mma16816(accp[mt][nt], ah[mt], bl);
                        mma16816(accp[mt][nt], al[mt], bh);
                    }
                }
            }
#pragma unroll
            for (int mt = 0; mt < 2; mt++)
#pragma unroll
                for (int nt = 0; nt < 4; nt++) {
                    int rA = m0 + mt * 16 + (lane >> 2);
                    int rB = rA + 8;
                    int c = half * 128 + nw0 + nt * 8 + 2 * (lane & 3);
                    int nA = n0 + rA, nB = n0 + rB;
                    if (nA < NN) {
                        g_pre[(u64)nA * 256 + c]     = accp[mt][nt][0];
                        g_pre[(u64)nA * 256 + c + 1] = accp[mt][nt][1];
                    }
                    if (nB < NN) {
                        g_pre[(u64)nB * 256 + c]     = accp[mt][nt][2];
                        g_pre[(u64)nB * 256 + c + 1] = accp[mt][nt][3];
                    }
                }
            __syncthreads();
        }
    }
}

// ---------------- final readout ----------------
__global__ void k_final(const float* __restrict__ gc,
                        const float* __restrict__ qw1,
                        const float* __restrict__ qb1,
                        const float* __restrict__ qw2,
                        const float* __restrict__ qb2p,
                        float* __restrict__ out) {
    __shared__ float sA[32 * 33];
    __shared__ float sW[128 * 33];
    __shared__ float sctx[64];
    __shared__ float sout[32];
    int tid = threadIdx.x;
    int n0 = blockIdx.x * 32;
    if (tid < 64) sctx[tid] = gc[tid];
    if (tid < 32) sout[tid] = qb2p[0];
    __syncthreads();
    int tc = tid & 31, trg = tid >> 5;
    float acc[4][4] = {};
    for (int kb = 0; kb < 192; kb += 32) {
        for (int idx = tid; idx < 32 * 32; idx += NT) {
            int r = idx >> 5, kk = idx & 31;
            int n = n0 + r;
            int kg = kb + kk;
            float v = 0.f;
            if (n < NN) v = (kg < 128) ? g_h[n * HID + kg] : sctx[kg - 128];
            sA[r * 33 + kk] = v;
        }
        for (int idx = tid; idx < 128 * 32; idx += NT) {
            int o = idx >> 5, kk = idx & 31;
            sW[o * 33 + kk] = qw1[o * 192 + kb + kk];
        }
        __syncthreads();
#pragma unroll 8
        for (int k = 0; k < 32; k++) {
            float a[4], w[4];
#pragma unroll
            for (int i = 0; i < 4; i++) a[i] = sA[(trg * 4 + i) * 33 + k];
#pragma unroll
            for (int j = 0; j < 4; j++) w[j] = sW[(tc + 32 * j) * 33 + k];
#pragma unroll
            for (int i = 0; i < 4; i++)
#pragma unroll
                for (int j = 0; j < 4; j++) acc[i][j] += a[i] * w[j];
        }
        __syncthreads();
    }
    float p[4] = {0.f, 0.f, 0.f, 0.f};
#pragma unroll
    for (int j = 0; j < 4; j++) {
        int c = tc + 32 * j;
        float b = qb1[c], w2 = qw2[c];
#pragma unroll
        for (int i = 0; i < 4; i++) {
            float v = fmaxf(acc[i][j] + b, 0.f);
            p[i] += v * w2;
        }
    }
#pragma unroll
    for (int i = 0; i < 4; i++) atomicAdd(&sout[trg * 4 + i], p[i]);
    __syncthreads();
    if (tid < 32) {
        int n = n0 + tid;
        if (n < NN) out[n] = sout[tid];
    }
}

// ---------------- launch ----------------
extern "C" void kernel_launch(void* const* d_in, const int* in_sizes, int n_in,
                              void* d_out, int out_size) {
    const float* x    = (const float*)d_in[0];
    const void*  eidx = d_in[1];
    const float* ea   = (const float*)d_in[2];
    const float* gc   = (const float*)d_in[3];
    const float* npw  = (const float*)d_in[4];
    const float* npb  = (const float*)d_in[5];
    const float* mw1  = (const float*)d_in[6];
    const float* mb1  = (const float*)d_in[7];
    const float* mw2  = (const float*)d_in[8];
    const float* mb2  = (const float*)d_in[9];
    const float* aw1  = (const float*)d_in[10];
    const float* ab1  = (const float*)d_in[11];
    const float* aw2  = (const float*)d_in[12];
    const float* ab2  = (const float*)d_in[13];
    const float* uw1  = (const float*)d_in[14];
    const float* ub1  = (const float*)d_in[15];
    const float* uw2  = (const float*)d_in[16];
    const float* ub2  = (const float*)d_in[17];
    const float* lng  = (const float*)d_in[18];
    const float* lnb  = (const float*)d_in[19];
    const float* qw1  = (const float*)d_in[20];
    const float* qb1  = (const float*)d_in[21];
    const float* qw2  = (const float*)d_in[22];
    const float* qb2  = (const float*)d_in[23];
    float* out = (float*)d_out;

    cudaFuncSetAttribute(k_msg, cudaFuncAttributeMaxDynamicSharedMemorySize, SMEM_MSG2);
    cudaFuncSetAttribute(k_node_pre, cudaFuncAttributeMaxDynamicSharedMemorySize, SMEM_NP);
    cudaFuncSetAttribute(k_update, cudaFuncAttributeMaxDynamicSharedMemorySize, SMEM_UPD);

    int prep_tot = 3 * (256 * 128 + 192 * 16 + 128 * 128 + 256 * 128 + 128 * 128);
    k_prep<<<(prep_tot + 255) / 256, 256>>>(mw1, mw2, aw1, uw1, uw2);
    k_detect<<<1, NT>>>((const unsigned*)eidx);
    k_convert<<<(NE + NT - 1) / NT, NT>>>(eidx, ea);
    k_hist<<<(NE + 255) / 256, 256>>>();
    k_scan<<<1, 1024>>>();
    k_scatter<<<(NE + 255) / 256, 256>>>();
    k_nodeproj<<<(NN + 31) / 32, NT>>>(x, npw, npb);

    int ngrid = (NN + 63) / 64;
    k_node_pre<<<ngrid, 256, SMEM_NP>>>(0);
    for (int l = 0; l < 3; l++) {
        k_attn_lite<<<(NE + 63) / 64, 256>>>(ea, aw1 + l * 64 * 272, ab1 + l * 64,
                                             aw2 + l * 64, ab2 + l, l);
        k_exp<<<(NE + NT - 1) / NT, NT>>>(l);
        k_msg<<<MSG_GRID, 256, SMEM_MSG2>>>(mb1 + l * 128, mb2 + l * 128, l);
        k_update<<<ngrid, 256, SMEM_UPD>>>(ub1 + l * 128, ub2 + l * 128,
                                           lng + l * 128, lnb + l * 128, l,
                                           (l < 2) ? 1 : 0);
    }
    k_final<<<(NN + 31) / 32, NT>>>(gc, qw1, qb1, qw2, qb2, out);
}

// round 15
// speedup vs baseline: 1.1012x; 1.1012x over previous
#include <cuda_runtime.h>
#include <cuda_bf16.h>

#define NN 50000
#define NE 600000
#define HID 128
#define NT 256

typedef unsigned long long u64;
typedef unsigned int u32;
typedef unsigned short u16;

// ---------------- scratch ----------------
__device__ float g_h[NN * HID];
__device__ float g_pre[NN * 256];      // [0:64)=u_s, [64:128)=u_d, [128:256)=vh
__device__ float g_msgbuf[(u64)NE * 128];
__device__ float g_sumexp[3 * NN];
__device__ float g_scores[NE];
__device__ float g_es[NE];
__device__ int   g_src[NE];
__device__ int   g_dst[NE];
__device__ unsigned g_maxenc[3];
__device__ int   g_is64;
// CSR by dst
__device__ int g_cnt[NN];
__device__ int g_row[NN];
__device__ int g_cur[NN];
__device__ int g_eord[NE];
// bf16 hi/lo splits
__device__ __align__(16) u16 g_hh[NN * HID];
__device__ __align__(16) u16 g_hl[NN * HID];
__device__ __align__(16) u16 g_eah[NE * 16];
__device__ __align__(16) u16 g_eal[NE * 16];
__device__ __align__(16) u16 g_NPh[3 * 256 * 128];
__device__ __align__(16) u16 g_NPl[3 * 256 * 128];
__device__ __align__(16) u16 g_EWh[3 * 192 * 16];
__device__ __align__(16) u16 g_EWl[3 * 192 * 16];
__device__ __align__(16) u16 g_W2h[3 * 128 * 128];
__device__ __align__(16) u16 g_W2l[3 * 128 * 128];
__device__ __align__(16) u16 g_U1h[3 * 256 * 128];
__device__ __align__(16) u16 g_U1l[3 * 256 * 128];
__device__ __align__(16) u16 g_U2h[3 * 128 * 128];
__device__ __align__(16) u16 g_U2l[3 * 128 * 128];

__device__ __forceinline__ unsigned fenc(float f) {
    unsigned u = __float_as_uint(f);
    return (u & 0x80000000u) ? ~u : (u | 0x80000000u);
}
__device__ __forceinline__ float fdec(unsigned u) {
    return (u & 0x80000000u) ? __uint_as_float(u & 0x7fffffffu)
                             : __uint_as_float(~u);
}

// ---------------- streaming mem helpers ----------------
__device__ __forceinline__ void stcs_f2(float* p, float2 v) {
    asm volatile("st.global.cs.v2.f32 [%0], {%1, %2};"
                 :: "l"(p), "f"(v.x), "f"(v.y) : "memory");
}
__device__ __forceinline__ float4 ldcs_f4(const float* p) {
    float4 v;
    asm volatile("ld.global.cs.v4.f32 {%0, %1, %2, %3}, [%4];"
                 : "=f"(v.x), "=f"(v.y), "=f"(v.z), "=f"(v.w) : "l"(p));
    return v;
}

// ---------------- bf16 split helpers ----------------
__device__ __forceinline__ void split_bf16(float v, u16 &h, u16 &l) {
    __nv_bfloat16 bh = __float2bfloat16(v);
    __nv_bfloat16 bl = __float2bfloat16(v - __bfloat162float(bh));
    h = __bfloat16_as_ushort(bh);
    l = __bfloat16_as_ushort(bl);
}
__device__ __forceinline__ void split2(float a, float b, u32 &h, u32 &l) {
    u16 h0, l0, h1, l1;
    split_bf16(a, h0, l0);
    split_bf16(b, h1, l1);
    h = (u32)h0 | ((u32)h1 << 16);
    l = (u32)l0 | ((u32)l1 << 16);
}

// ---------------- HMMA helpers ----------------
__device__ __forceinline__ u32 smem_u32(const void* p) {
    u32 a;
    asm("{ .reg .u64 t; cvta.to.shared.u64 t, %1; cvt.u32.u64 %0, t; }"
        : "=r"(a) : "l"(p));
    return a;
}
__device__ __forceinline__ void ldsm4(u32* r, u32 addr) {
    asm volatile("ldmatrix.sync.aligned.m8n8.x4.shared.b16 {%0,%1,%2,%3}, [%4];"
        : "=r"(r[0]), "=r"(r[1]), "=r"(r[2]), "=r"(r[3]) : "r"(addr));
}
__device__ __forceinline__ void ldsm2(u32* r, u32 addr) {
    asm volatile("ldmatrix.sync.aligned.m8n8.x2.shared.b16 {%0,%1}, [%2];"
        : "=r"(r[0]), "=r"(r[1]) : "r"(addr));
}
__device__ __forceinline__ void mma16816(float* d, const u32* a, const u32* b) {
    asm volatile("mma.sync.aligned.m16n8k16.row.col.f32.bf16.bf16.f32 "
        "{%0,%1,%2,%3}, {%4,%5,%6,%7}, {%8,%9}, {%0,%1,%2,%3};"
        : "+f"(d[0]), "+f"(d[1]), "+f"(d[2]), "+f"(d[3])
        : "r"(a[0]), "r"(a[1]), "r"(a[2]), "r"(a[3]), "r"(b[0]), "r"(b[1]));
}

// ---------------- weight preconversion ----------------
__global__ void k_prep(const float* __restrict__ mw1, const float* __restrict__ mw2,
                       const float* __restrict__ aw1, const float* __restrict__ uw1,
                       const float* __restrict__ uw2) {
    int idx = blockIdx.x * blockDim.x + threadIdx.x;
    const int NP = 3 * 256 * 128, EW = 3 * 192 * 16, W2 = 3 * 128 * 128;
    const int U1 = 3 * 256 * 128, U2 = 3 * 128 * 128;
    u16 h, l;
    if (idx < NP) {
        int lyr = idx / (256 * 128);
        int rem = idx % (256 * 128);
        int n = rem / 128, k = rem % 128;
        float v;
        if (n < 64)        v = aw1[lyr * 64 * 272 + n * 272 + k];
        else if (n < 128)  v = aw1[lyr * 64 * 272 + (n - 64) * 272 + 128 + k];
        else               v = mw1[lyr * 128 * 144 + (n - 128) * 144 + k];
        split_bf16(v, h, l);
        g_NPh[idx] = h; g_NPl[idx] = l;
    } else if (idx < NP + EW) {
        int i = idx - NP;
        int lyr = i / (192 * 16);
        int rem = i % (192 * 16);
        int n = rem / 16, k = rem % 16;
        float v = (n < 64) ? aw1[lyr * 64 * 272 + n * 272 + 256 + k]
                           : mw1[lyr * 128 * 144 + (n - 64) * 144 + 128 + k];
        split_bf16(v, h, l);
        g_EWh[i] = h; g_EWl[i] = l;
    } else if (idx < NP + EW + W2) {
        int i = idx - NP - EW;
        split_bf16(mw2[i], h, l);
        g_W2h[i] = h; g_W2l[i] = l;
    } else if (idx < NP + EW + W2 + U1) {
        int i = idx - NP - EW - W2;
        int lyr = i / 32768;
        int rem = i % 32768;
        int half = rem / 16384;
        int r2 = rem % 16384;
        int n = r2 / 128, k = r2 % 128;
        split_bf16(uw1[lyr * 32768 + n * 256 + half * 128 + k], h, l);
        g_U1h[i] = h; g_U1l[i] = l;
    } else if (idx < NP + EW + W2 + U1 + U2) {
        int i = idx - NP - EW - W2 - U1;
        split_bf16(uw2[i], h, l);
        g_U2h[i] = h; g_U2l[i] = l;
    }
}

// ---------------- detect + convert + ea split + zero ----------------
__global__ void k_detect(const unsigned* __restrict__ raw) {
    __shared__ int nz;
    if (threadIdx.x == 0) nz = 0;
    __syncthreads();
    for (int i = threadIdx.x; i < 2048; i += NT)
        if (raw[2 * i + 1] != 0u) atomicOr(&nz, 1);
    __syncthreads();
    if (threadIdx.x == 0) g_is64 = (nz == 0) ? 1 : 0;
}

__global__ void k_convert(const void* __restrict__ eidx, const float* __restrict__ ea) {
    int i = blockIdx.x * blockDim.x + threadIdx.x;
    long long stride = (long long)gridDim.x * blockDim.x;
    if (i < NE) {
        if (g_is64) {
            const long long* p = (const long long*)eidx;
            g_src[i] = (int)p[i];
            g_dst[i] = (int)p[NE + i];
        } else {
            const int* p = (const int*)eidx;
            g_src[i] = p[i];
            g_dst[i] = p[NE + i];
        }
    }
    for (long long j = i; j < (long long)NE * 16; j += stride) {
        u16 h, l;
        split_bf16(ea[j], h, l);
        g_eah[j] = h; g_eal[j] = l;
    }
    for (long long j = i; j < 3 * NN; j += stride) g_sumexp[j] = 0.f;
    for (long long j = i; j < NN; j += stride) g_cnt[j] = 0;
    if (i == 0) {
        g_maxenc[0] = 0x007FFFFFu;
        g_maxenc[1] = 0x007FFFFFu;
        g_maxenc[2] = 0x007FFFFFu;
    }
}

// ---------------- counting sort by dst (CSR) ----------------
__global__ void k_hist() {
    int i = blockIdx.x * blockDim.x + threadIdx.x;
    if (i < NE) atomicAdd(&g_cnt[g_dst[i]], 1);
}

__global__ void k_scan() {
    __shared__ int warpsum[32];
    __shared__ int scarry;
    int tid = threadIdx.x, lane = tid & 31, wid = tid >> 5;
    if (tid == 0) scarry = 0;
    __syncthreads();
    for (int base = 0; base < NN; base += 1024) {
        int i = base + tid;
        int v = (i < NN) ? g_cnt[i] : 0;
        int s = v;
#pragma unroll
        for (int off = 1; off < 32; off <<= 1) {
            int t = __shfl_up_sync(0xffffffffu, s, off);
            if (lane >= off) s += t;
        }
        if (lane == 31) warpsum[wid] = s;
        __syncthreads();
        if (wid == 0) {
            int ws = warpsum[lane];
#pragma unroll
            for (int off = 1; off < 32; off <<= 1) {
                int t = __shfl_up_sync(0xffffffffu, ws, off);
                if (lane >= off) ws += t;
            }
            warpsum[lane] = ws;
        }
        __syncthreads();
        int incl = s + (wid > 0 ? warpsum[wid - 1] : 0) + scarry;
        if (i < NN) { g_row[i] = incl - v; g_cur[i] = incl - v; }
        __syncthreads();
        if (tid == 1023) scarry = incl;
        __syncthreads();
    }
}

__global__ void k_scatter() {
    int i = blockIdx.x * blockDim.x + threadIdx.x;
    if (i < NE) {
        int pos = atomicAdd(&g_cur[g_dst[i]], 1);
        g_eord[pos] = i;
    }
}

// ---------------- node projection (+ split store) ----------------
__global__ void k_nodeproj(const float* __restrict__ x,
                           const float* __restrict__ W,
                           const float* __restrict__ b) {
    __shared__ float sA[32 * 33];
    __shared__ float sW[128 * 33];
    int tid = threadIdx.x;
    int n0 = blockIdx.x * 32;
    for (int idx = tid; idx < 32 * 32; idx += NT) {
        int r = idx >> 5, k = idx & 31;
        int n = n0 + r;
        sA[r * 33 + k] = (n < NN) ? x[n * 32 + k] : 0.f;
    }
    for (int idx = tid; idx < 128 * 32; idx += NT) {
        int o = idx >> 5, k = idx & 31;
        sW[o * 33 + k] = W[o * 32 + k];
    }
    __syncthreads();
    int tc = tid & 31, trg = tid >> 5;
    float acc[4][4] = {};
#pragma unroll 8
    for (int k = 0; k < 32; k++) {
        float a[4], w[4];
#pragma unroll
        for (int i = 0; i < 4; i++) a[i] = sA[(trg * 4 + i) * 33 + k];
#pragma unroll
        for (int j = 0; j < 4; j++) w[j] = sW[(tc + 32 * j) * 33 + k];
#pragma unroll
        for (int i = 0; i < 4; i++)
#pragma unroll
            for (int j = 0; j < 4; j++) acc[i][j] += a[i] * w[j];
    }
#pragma unroll
    for (int i = 0; i < 4; i++) {
        int n = n0 + trg * 4 + i;
        if (n < NN)
#pragma unroll
            for (int j = 0; j < 4; j++) {
                int c = tc + 32 * j;
                float v = fmaxf(acc[i][j] + b[c], 0.f);
                g_h[n * HID + c] = v;
                u16 h, l;
                split_bf16(v, h, l);
                g_hh[n * HID + c] = h;
                g_hl[n * HID + c] = l;
            }
    }
}

// ---------------- node precompute GEMM: M=64 tiles, 2 CTAs/SM (layer 0 only) ----------------
#define NPP 136
#define NP_AH 0
#define NP_AL 17408
#define NP_WH 34816
#define NP_WL 69632
#define SMEM_NP 104448

__global__ void __launch_bounds__(256, 2)
k_node_pre(int layer) {
    extern __shared__ char sm[];
    u16* sAh = (u16*)(sm + NP_AH);
    u16* sAl = (u16*)(sm + NP_AL);
    u16* sWh = (u16*)(sm + NP_WH);
    u16* sWl = (u16*)(sm + NP_WL);
    u32 sb = smem_u32(sm);
    int tid = threadIdx.x, lane = tid & 31, w = tid >> 5;
    int n0 = blockIdx.x * 64;

    for (int idx = tid; idx < 64 * 16; idx += 256) {
        int r = idx >> 4, c = (idx & 15) * 8;
        int n = n0 + r;
        if (n < NN) {
            *(uint4*)&sAh[r * NPP + c] = *(const uint4*)&g_hh[n * HID + c];
            *(uint4*)&sAl[r * NPP + c] = *(const uint4*)&g_hl[n * HID + c];
        } else {
            uint4 z = make_uint4(0, 0, 0, 0);
            *(uint4*)&sAh[r * NPP + c] = z;
            *(uint4*)&sAl[r * NPP + c] = z;
        }
    }

    int m0 = (w & 1) * 32, n0w = (w >> 1) * 32;
    for (int half = 0; half < 2; half++) {
        const u16* wh = g_NPh + layer * 256 * 128 + half * 128 * 128;
        const u16* wl = g_NPl + layer * 256 * 128 + half * 128 * 128;
        for (int idx = tid; idx < 128 * 16; idx += 256) {
            int r = idx >> 4, c = (idx & 15) * 8;
            *(uint4*)&sWh[r * NPP + c] = *(const uint4*)&wh[r * 128 + c];
            *(uint4*)&sWl[r * NPP + c] = *(const uint4*)&wl[r * 128 + c];
        }
        __syncthreads();
        float acc[2][4][4];
#pragma unroll
        for (int i = 0; i < 2; i++)
#pragma unroll
            for (int j = 0; j < 4; j++)
#pragma unroll
                for (int k = 0; k < 4; k++) acc[i][j][k] = 0.f;
        for (int ks = 0; ks < 8; ks++) {
            int kb = ks * 16;
            u32 ah[2][4], al[2][4];
#pragma unroll
            for (int mt = 0; mt < 2; mt++) {
                int r = m0 + mt * 16 + (lane & 15);
                int c = kb + ((lane >> 4) << 3);
                u32 off = (u32)(r * NPP + c) * 2;
                ldsm4(ah[mt], sb + NP_AH + off);
                ldsm4(al[mt], sb + NP_AL + off);
            }
#pragma unroll
            for (int nt = 0; nt < 4; nt++) {
                int rn = n0w + nt * 8 + (lane & 7);
                int cn = kb + (((lane >> 3) & 1) << 3);
                u32 offb = (u32)(rn * NPP + cn) * 2;
                u32 bh[2], bl[2];
                ldsm2(bh, sb + NP_WH + offb);
                ldsm2(bl, sb + NP_WL + offb);
#pragma unroll
                for (int mt = 0; mt < 2; mt++) {
                    mma16816(acc[mt][nt], ah[mt], bh);
                    mma16816(acc[mt][nt], ah[mt], bl);
                    mma16816(acc[mt][nt], al[mt], bh);
                }
            }
        }
#pragma unroll
        for (int mt = 0; mt < 2; mt++)
#pragma unroll
            for (int nt = 0; nt < 4; nt++) {
                int rA = m0 + mt * 16 + (lane >> 2);
                int rB = rA + 8;
                int c = half * 128 + n0w + nt * 8 + 2 * (lane & 3);
                int nA = n0 + rA, nB = n0 + rB;
                if (nA < NN) {
                    g_pre[(u64)nA * 256 + c]     = acc[mt][nt][0];
                    g_pre[(u64)nA * 256 + c + 1] = acc[mt][nt][1];
                }
                if (nB < NN) {
                    g_pre[(u64)nB * 256 + c]     = acc[mt][nt][2];
                    g_pre[(u64)nB * 256 + c + 1] = acc[mt][nt][3];
                }
            }
        __syncthreads();
    }
}

// ---------------- attention scores (elementwise, decomposed) ----------------
__global__ void __launch_bounds__(256, 4)
k_attn_lite(const float* __restrict__ ea,
            const float* __restrict__ aw1l,
            const float* __restrict__ ab1,
            const float* __restrict__ aw2,
            const float* __restrict__ ab2p, int layer) {
    __shared__ float sea[64 * 17];
    __shared__ float sW[64 * 16];
    __shared__ float sb1[64], sv[64];
    __shared__ unsigned smax;
    int tid = threadIdx.x;
    int e0 = blockIdx.x * 64;
    if (tid == 0) smax = 0x007FFFFFu;
    {
        int r = tid >> 2, c = (tid & 3) * 4;
        float4 v = make_float4(0.f, 0.f, 0.f, 0.f);
        if (e0 + r < NE) v = *(const float4*)&ea[(u64)(e0 + r) * 16 + c];
        sea[r * 17 + c]     = v.x;
        sea[r * 17 + c + 1] = v.y;
        sea[r * 17 + c + 2] = v.z;
        sea[r * 17 + c + 3] = v.w;
    }
    {
        int r = tid >> 2, c = (tid & 3) * 4;
        float4 wv = *(const float4*)&aw1l[r * 272 + 256 + c];
        *(float4*)&sW[r * 16 + c] = wv;
    }
    if (tid < 64) { sb1[tid] = ab1[tid]; sv[tid] = aw2[tid]; }
    __syncthreads();

    int el = tid >> 2, p = tid & 3;
    int e = e0 + el;
    float score = 0.f;
    if (e < NE) {
        int s = g_src[e], d = g_dst[e];
        const float* ps = &g_pre[(u64)s * 256 + p * 16];
        const float* pd = &g_pre[(u64)d * 256 + 64 + p * 16];
        const float* er = &sea[el * 17];
#pragma unroll
        for (int c4 = 0; c4 < 4; c4++) {
            float4 a4 = *(const float4*)&ps[c4 * 4];
            float4 b4 = *(const float4*)&pd[c4 * 4];
            float av[4] = {a4.x, a4.y, a4.z, a4.w};
            float bv[4] = {b4.x, b4.y, b4.z, b4.w};
#pragma unroll
            for (int j = 0; j < 4; j++) {
                int c = p * 16 + c4 * 4 + j;
                float x = av[j] + bv[j] + sb1[c];
                const float* wr = &sW[c * 16];
#pragma unroll
                for (int k = 0; k < 16; k++) x += er[k] * wr[k];
                x = (x > 0.f) ? x : 0.2f * x;
                score += x * sv[c];
            }
        }
    }
    score += __shfl_xor_sync(0xffffffffu, score, 1);
    score += __shfl_xor_sync(0xffffffffu, score, 2);
    if (p == 0 && e < NE) {
        float sc = score + ab2p[0];
        g_scores[e] = sc;
        atomicMax(&smax, fenc(sc));
    }
    __syncthreads();
    if (tid == 0) atomicMax(&g_maxenc[layer], smax);
}

// ---------------- exp + scatter sum ----------------
__global__ void k_exp(int layer) {
    int i = blockIdx.x * blockDim.x + threadIdx.x;
    if (i >= NE) return;
    float m = fdec(g_maxenc[layer]);
    float es = __expf(g_scores[i] - m);
    g_es[i] = es;
    atomicAdd(&g_sumexp[layer * NN + g_dst[i]], es);
}

// ---------------- message MLP: persistent weights, grid-stride tiles ----------------
#define AP2 136
#define M_AH 0
#define M_AL 17408
#define M_WH 34816
#define M_WL 69632
#define M_META 104448
#define SMEM_MSG2 (104448 + 1536)
#define NTILES ((NE + 63) / 64)

__global__ void __launch_bounds__(256, 2)
k_msg(const float* __restrict__ mb1,
      const float* __restrict__ mb2, int layer) {
    extern __shared__ char sm[];
    u16* sAh = (u16*)(sm + M_AH);
    u16* sAl = (u16*)(sm + M_AL);
    u16* sWh = (u16*)(sm + M_WH);
    u16* sWl = (u16*)(sm + M_WL);
    int*   ssrc = (int*)(sm + M_META);
    float* swt  = (float*)(sm + M_META + 256);
    float* smb1 = (float*)(sm + M_META + 512);
    float* smb2 = (float*)(sm + M_META + 1024);
    u32 sb = smem_u32(sm);

    int tid = threadIdx.x, lane = tid & 31, w = tid >> 5;
    int m0 = (w & 1) * 32, n0 = (w >> 1) * 32;

    // ---- one-time setup: stage Wea (compact stride 16) in A area, load W2, biases ----
    {
        const u16* wh = g_EWh + layer * 192 * 16 + 64 * 16;
        const u16* wl = g_EWl + layer * 192 * 16 + 64 * 16;
        for (int idx = tid; idx < 128 * 2; idx += 256) {
            int r = idx >> 1, c = (idx & 1) * 8;
            *(uint4*)&sAh[r * 16 + c] = *(const uint4*)&wh[r * 16 + c];
            *(uint4*)&sAl[r * 16 + c] = *(const uint4*)&wl[r * 16 + c];
        }
        const u16* w2h = g_W2h + layer * 128 * 128;
        const u16* w2l = g_W2l + layer * 128 * 128;
        for (int idx = tid; idx < 128 * 16; idx += 256) {
            int r = idx >> 4, c = (idx & 15) * 8;
            *(uint4*)&sWh[r * AP2 + c] = *(const uint4*)&w2h[r * 128 + c];
            *(uint4*)&sWl[r * AP2 + c] = *(const uint4*)&w2l[r * 128 + c];
        }
        if (tid < 128) { smb1[tid] = mb1[tid]; smb2[tid] = mb2[tid]; }
    }
    __syncthreads();
    // Wea fragments -> registers (held across all tiles)
    u32 weah[4][2], weal[4][2];
#pragma unroll
    for (int nt = 0; nt < 4; nt++) {
        int rn = n0 + nt * 8 + (lane & 7);
        int cn = ((lane >> 3) & 1) << 3;
        u32 off = (u32)(rn * 16 + cn) * 2;
        ldsm2(weah[nt], sb + M_AH + off);
        ldsm2(weal[nt], sb + M_AL + off);
    }
    __syncthreads();

    for (int t = blockIdx.x; t < NTILES; t += gridDim.x) {
        int e0 = t * 64;
        if (tid < 64) {
            int e = e0 + tid;
            if (e < NE) {
                ssrc[tid] = g_src[e];
                int d = g_dst[e];
                swt[tid] = g_es[e] / (g_sumexp[layer * NN + d] + 1e-6f);
            } else {
                ssrc[tid] = 0; swt[tid] = 0.f;
            }
        }
        // ea split -> A tile cols 0..15
        for (int idx = tid; idx < 64 * 2; idx += 256) {
            int r = idx >> 1, c = (idx & 1) * 8;
            int e = min(e0 + r, NE - 1);
            *(uint4*)&sAh[r * AP2 + c] = *(const uint4*)&g_eah[(u64)e * 16 + c];
            *(uint4*)&sAl[r * AP2 + c] = *(const uint4*)&g_eal[(u64)e * 16 + c];
        }
        __syncthreads();

        // GEMM_ea: K=16, Wea from registers
        float acc[2][4][4];
#pragma unroll
        for (int i = 0; i < 2; i++)
#pragma unroll
            for (int j = 0; j < 4; j++)
#pragma unroll
                for (int k = 0; k < 4; k++) acc[i][j][k] = 0.f;
        {
            u32 ah[2][4], al[2][4];
#pragma unroll
            for (int mt = 0; mt < 2; mt++) {
                int r = m0 + mt * 16 + (lane & 15);
                int c = (lane >> 4) << 3;
                u32 off = (u32)(r * AP2 + c) * 2;
                ldsm4(ah[mt], sb + M_AH + off);
                ldsm4(al[mt], sb + M_AL + off);
            }
#pragma unroll
            for (int nt = 0; nt < 4; nt++) {
#pragma unroll
                for (int mt = 0; mt < 2; mt++) {
                    mma16816(acc[mt][nt], ah[mt], weah[nt]);
                    mma16816(acc[mt][nt], ah[mt], weal[nt]);
                    mma16816(acc[mt][nt], al[mt], weah[nt]);
                }
            }
        }
        __syncthreads();

        // epilogue-ea: m = relu(eaW + vh + b1) -> split into A tiles (vh direct from L2)
#pragma unroll
        for (int mt = 0; mt < 2; mt++)
#pragma unroll
            for (int nt = 0; nt < 4; nt++) {
                int rA = m0 + mt * 16 + (lane >> 2);
                int rB = rA + 8;
                int c = n0 + nt * 8 + 2 * (lane & 3);
                float b0 = smb1[c], b1 = smb1[c + 1];
                float2 vA = *(const float2*)&g_pre[(u64)ssrc[rA] * 256 + 128 + c];
                float2 vB = *(const float2*)&g_pre[(u64)ssrc[rB] * 256 + 128 + c];
                u32 h, l;
                split2(fmaxf(acc[mt][nt][0] + vA.x + b0, 0.f),
                       fmaxf(acc[mt][nt][1] + vA.y + b1, 0.f), h, l);
                *(u32*)&sAh[rA * AP2 + c] = h;
                *(u32*)&sAl[rA * AP2 + c] = l;
                split2(fmaxf(acc[mt][nt][2] + vB.x + b0, 0.f),
                       fmaxf(acc[mt][nt][3] + vB.y + b1, 0.f), h, l);
                *(u32*)&sAh[rB * AP2 + c] = h;
                *(u32*)&sAl[rB * AP2 + c] = l;
            }
        __syncthreads();

        // GEMM2 K=128 (W2 resident)
        float acc2[2][4][4];
#pragma unroll
        for (int i = 0; i < 2; i++)
#pragma unroll
            for (int j = 0; j < 4; j++)
#pragma unroll
                for (int k = 0; k < 4; k++) acc2[i][j][k] = 0.f;

        for (int ks = 0; ks < 8; ks++) {
            int kb = ks * 16;
            u32 ah[2][4], al[2][4];
#pragma unroll
            for (int mt = 0; mt < 2; mt++) {
                int r = m0 + mt * 16 + (lane & 15);
                int c = kb + ((lane >> 4) << 3);
                u32 off = (u32)(r * AP2 + c) * 2;
                ldsm4(ah[mt], sb + M_AH + off);
                ldsm4(al[mt], sb + M_AL + off);
            }
#pragma unroll
            for (int nt = 0; nt < 4; nt++) {
                int rn = n0 + nt * 8 + (lane & 7);
                int cn = kb + (((lane >> 3) & 1) << 3);
                u32 offb = (u32)(rn * AP2 + cn) * 2;
                u32 bh[2], bl[2];
                ldsm2(bh, sb + M_WH + offb);
                ldsm2(bl, sb + M_WL + offb);
#pragma unroll
                for (int mt = 0; mt < 2; mt++) {
                    mma16816(acc2[mt][nt], ah[mt], bh);
                    mma16816(acc2[mt][nt], ah[mt], bl);
                    mma16816(acc2[mt][nt], al[mt], bh);
                }
            }
        }

        // epilogue2: weighted message -> streaming store to g_msgbuf
#pragma unroll
        for (int mt = 0; mt < 2; mt++)
#pragma unroll
            for (int nt = 0; nt < 4; nt++) {
                int rA = m0 + mt * 16 + (lane >> 2);
                int rB = rA + 8;
                int c = n0 + nt * 8 + 2 * (lane & 3);
                float b0 = smb2[c], b1 = smb2[c + 1];
                float wA = swt[rA], wB = swt[rB];
                int eA = e0 + rA, eB = e0 + rB;
                if (eA < NE) {
                    float2 v;
                    v.x = (acc2[mt][nt][0] + b0) * wA;
                    v.y = (acc2[mt][nt][1] + b1) * wA;
                    stcs_f2(&g_msgbuf[(u64)eA * 128 + c], v);
                }
                if (eB < NE) {
                    float2 v;
                    v.x = (acc2[mt][nt][2] + b0) * wB;
                    v.y = (acc2[mt][nt][3] + b1) * wB;
                    stcs_f2(&g_msgbuf[(u64)eB * 128 + c], v);
                }
            }
        __syncthreads();
    }
}

// ---------------- node update: CSR gather + HMMA MLP + LN + fused pre ----------------
#define UPP 136
#define U_AH 0
#define U_AL 17408
#define U_WH 34816
#define U_WL 69632
#define SMEM_UPD 104448

__global__ void __launch_bounds__(256, 2)
k_update(const float* __restrict__ ub1,
         const float* __restrict__ ub2,
         const float* __restrict__ lng,
         const float* __restrict__ lnb, int layer, int do_pre) {
    extern __shared__ char sm[];
    u16* sAh = (u16*)(sm + U_AH);
    u16* sAl = (u16*)(sm + U_AL);
    u16* sWh = (u16*)(sm + U_WH);
    u16* sWl = (u16*)(sm + U_WL);
    float* stage = (float*)(sm + U_WH);
    u32 sb = smem_u32(sm);
    int tid = threadIdx.x, lane = tid & 31, w = tid >> 5;
    int n0 = blockIdx.x * 64;

    // phase 0: CSR gather of weighted messages (agg in registers, streaming loads)
    int ln = tid >> 2, q = tid & 3;
    int nn = n0 + ln;
    float agg[32];
#pragma unroll
    for (int t = 0; t < 32; t++) agg[t] = 0.f;
    if (nn < NN) {
        int j0 = g_row[nn], j1 = g_cur[nn];
        for (int j = j0; j < j1; j++) {
            int e = g_eord[j];
            const float* mp = &g_msgbuf[(u64)e * 128 + q * 32];
#pragma unroll
            for (int t = 0; t < 8; t++) {
                float4 v = ldcs_f4(&mp[t * 4]);
                agg[t * 4]     += v.x;
                agg[t * 4 + 1] += v.y;
                agg[t * 4 + 2] += v.z;
                agg[t * 4 + 3] += v.w;
            }
        }
    }

    // A1 = h split
    for (int idx = tid; idx < 64 * 16; idx += 256) {
        int r = idx >> 4, c = (idx & 15) * 8;
        int n = n0 + r;
        if (n < NN) {
            *(uint4*)&sAh[r * UPP + c] = *(const uint4*)&g_hh[n * HID + c];
            *(uint4*)&sAl[r * UPP + c] = *(const uint4*)&g_hl[n * HID + c];
        } else {
            uint4 z = make_uint4(0, 0, 0, 0);
            *(uint4*)&sAh[r * UPP + c] = z;
            *(uint4*)&sAl[r * UPP + c] = z;
        }
    }
    // Wa (uw1 in-half 0)
    {
        const u16* wh = g_U1h + layer * 32768;
        const u16* wl = g_U1l + layer * 32768;
        for (int idx = tid; idx < 128 * 16; idx += 256) {
            int r = idx >> 4, c = (idx & 15) * 8;
            *(uint4*)&sWh[r * UPP + c] = *(const uint4*)&wh[r * 128 + c];
            *(uint4*)&sWl[r * UPP + c] = *(const uint4*)&wl[r * 128 + c];
        }
    }
    __syncthreads();

    int m0 = (w & 1) * 32, nw0 = (w >> 1) * 32;
    float acc[2][4][4];
#pragma unroll
    for (int i = 0; i < 2; i++)
#pragma unroll
        for (int j = 0; j < 4; j++)
#pragma unroll
            for (int k = 0; k < 4; k++) acc[i][j][k] = 0.f;

    for (int ks = 0; ks < 8; ks++) {
        int kb = ks * 16;
        u32 ah[2][4], al[2][4];
#pragma unroll
        for (int mt = 0; mt < 2; mt++) {
            int r = m0 + mt * 16 + (lane & 15);
            int c = kb + ((lane >> 4) << 3);
            u32 off = (u32)(r * UPP + c) * 2;
            ldsm4(ah[mt], sb + U_AH + off);
            ldsm4(al[mt], sb + U_AL + off);
        }
#pragma unroll
        for (int nt = 0; nt < 4; nt++) {
            int rn = nw0 + nt * 8 + (lane & 7);
            int cn = kb + (((lane >> 3) & 1) << 3);
            u32 offb = (u32)(rn * UPP + cn) * 2;
            u32 bh[2], bl[2];
            ldsm2(bh, sb + U_WH + offb);
            ldsm2(bl, sb + U_WL + offb);
#pragma unroll
            for (int mt = 0; mt < 2; mt++) {
                mma16816(acc[mt][nt], ah[mt], bh);
                mma16816(acc[mt][nt], ah[mt], bl);
                mma16816(acc[mt][nt], al[mt], bh);
            }
        }
    }
    __syncthreads();

    // A2 = agg split; Wb (uw1 in-half 1)
    {
#pragma unroll
        for (int t = 0; t < 16; t++) {
            u32 h, l;
            split2(agg[2 * t], agg[2 * t + 1], h, l);
            *(u32*)&sAh[ln * UPP + q * 32 + 2 * t] = h;
            *(u32*)&sAl[ln * UPP + q * 32 + 2 * t] = l;
        }
        const u16* wh = g_U1h + layer * 32768 + 16384;
        const u16* wl = g_U1l + layer * 32768 + 16384;
        for (int idx = tid; idx < 128 * 16; idx += 256) {
            int r = idx >> 4, c = (idx & 15) * 8;
            *(uint4*)&sWh[r * UPP + c] = *(const uint4*)&wh[r * 128 + c];
            *(uint4*)&sWl[r * UPP + c] = *(const uint4*)&wl[r * 128 + c];
        }
    }
    __syncthreads();

    for (int ks = 0; ks < 8; ks++) {
        int kb = ks * 16;
        u32 ah[2][4], al[2][4];
#pragma unroll
        for (int mt = 0; mt < 2; mt++) {
            int r = m0 + mt * 16 + (lane & 15);
            int c = kb + ((lane >> 4) << 3);
            u32 off = (u32)(r * UPP + c) * 2;
            ldsm4(ah[mt], sb + U_AH + off);
            ldsm4(al[mt], sb + U_AL + off);
        }
#pragma unroll
        for (int nt = 0; nt < 4; nt++) {
            int rn = nw0 + nt * 8 + (lane & 7);
            int cn = kb + (((lane >> 3) & 1) << 3);
            u32 offb = (u32)(rn * UPP + cn) * 2;
            u32 bh[2], bl[2];
            ldsm2(bh, sb + U_WH + offb);
            ldsm2(bl, sb + U_WL + offb);
#pragma unroll
            for (int mt = 0; mt < 2; mt++) {
                mma16816(acc[mt][nt], ah[mt], bh);
                mma16816(acc[mt][nt], ah[mt], bl);
                mma16816(acc[mt][nt], al[mt], bh);
            }
        }
    }
    __syncthreads();

    // relu(acc + ub1) -> re-split into A tiles
#pragma unroll
    for (int mt = 0; mt < 2; mt++)
#pragma unroll
        for (int nt = 0; nt < 4; nt++) {
            int rA = m0 + mt * 16 + (lane >> 2);
            int rB = rA + 8;
            int c = nw0 + nt * 8 + 2 * (lane & 3);
            float b0 = ub1[c], b1 = ub1[c + 1];
            u32 h, l;
            split2(fmaxf(acc[mt][nt][0] + b0, 0.f),
                   fmaxf(acc[mt][nt][1] + b1, 0.f), h, l);
            *(u32*)&sAh[rA * UPP + c] = h;
            *(u32*)&sAl[rA * UPP + c] = l;
            split2(fmaxf(acc[mt][nt][2] + b0, 0.f),
                   fmaxf(acc[mt][nt][3] + b1, 0.f), h, l);
            *(u32*)&sAh[rB * UPP + c] = h;
            *(u32*)&sAl[rB * UPP + c] = l;
        }
    // W2 = uw2 split
    {
        const u16* wh = g_U2h + layer * 128 * 128;
        const u16* wl = g_U2l + layer * 128 * 128;
        for (int idx = tid; idx < 128 * 16; idx += 256) {
            int r = idx >> 4, c = (idx & 15) * 8;
            *(uint4*)&sWh[r * UPP + c] = *(const uint4*)&wh[r * 128 + c];
            *(uint4*)&sWl[r * UPP + c] = *(const uint4*)&wl[r * 128 + c];
        }
    }
    __syncthreads();

    float acc2[2][4][4];
#pragma unroll
    for (int i = 0; i < 2; i++)
#pragma unroll
        for (int j = 0; j < 4; j++)
#pragma unroll
            for (int k = 0; k < 4; k++) acc2[i][j][k] = 0.f;

    for (int ks = 0; ks < 8; ks++) {
        int kb = ks * 16;
        u32 ah[2][4], al[2][4];
#pragma unroll
        for (int mt = 0; mt < 2; mt++) {
            int r = m0 + mt * 16 + (lane & 15);
            int c = kb + ((lane >> 4) << 3);
            u32 off = (u32)(r * UPP + c) * 2;
            ldsm4(ah[mt], sb + U_AH + off);
            ldsm4(al[mt], sb + U_AL + off);
        }
#pragma unroll
        for (int nt = 0; nt < 4; nt++) {
            int rn = nw0 + nt * 8 + (lane & 7);
            int cn = kb + (((lane >> 3) & 1) << 3);
            u32 offb = (u32)(rn * UPP + cn) * 2;
            u32 bh[2], bl[2];
            ldsm2(bh, sb + U_WH + offb);
            ldsm2(bl, sb + U_WL + offb);
#pragma unroll
            for (int mt = 0; mt < 2; mt++) {
                mma16816(acc2[mt][nt], ah[mt], bh);
                mma16816(acc2[mt][nt], ah[mt], bl);
                mma16816(acc2[mt][nt], al[mt], bh);
            }
        }
    }
    __syncthreads();  // W tiles dead -> stage

#pragma unroll
    for (int mt = 0; mt < 2; mt++)
#pragma unroll
        for (int nt = 0; nt < 4; nt++) {
            int rA = m0 + mt * 16 + (lane >> 2);
            int rB = rA + 8;
            int c = nw0 + nt * 8 + 2 * (lane & 3);
            stage[rA * 132 + c]     = acc2[mt][nt][0];
            stage[rA * 132 + c + 1] = acc2[mt][nt][1];
            stage[rB * 132 + c]     = acc2[mt][nt][2];
            stage[rB * 132 + c + 1] = acc2[mt][nt][3];
        }
    __syncthreads();

    // LN: 4 threads per row (ln, q); also deposit split h into A tiles for fused pre
    {
        int c0 = q * 32;
        float v[32];
        float s = 0.f, sq = 0.f;
        if (nn < NN) {
#pragma unroll
            for (int t4 = 0; t4 < 8; t4++) {
                float4 hres = *(const float4*)&g_h[nn * HID + c0 + t4 * 4];
                float hr[4] = {hres.x, hres.y, hres.z, hres.w};
#pragma unroll
                for (int j = 0; j < 4; j++) {
                    int t = t4 * 4 + j;
                    float val = stage[ln * 132 + c0 + t] + ub2[c0 + t] + hr[j];
                    val = fmaxf(val, 0.f);
                    v[t] = val;
                    s += val;
                    sq += val * val;
                }
            }
        } else {
#pragma unroll
            for (int t = 0; t < 32; t++) v[t] = 0.f;
        }
        s  += __shfl_xor_sync(0xffffffffu, s, 1);
        s  += __shfl_xor_sync(0xffffffffu, s, 2);
        sq += __shfl_xor_sync(0xffffffffu, sq, 1);
        sq += __shfl_xor_sync(0xffffffffu, sq, 2);
        float mu = s * (1.f / 128.f);
        float var = sq * (1.f / 128.f) - mu * mu;
        float rs = rsqrtf(var + 1e-5f);
        float o[32];
#pragma unroll
        for (int t = 0; t < 32; t++)
            o[t] = (v[t] - mu) * rs * lng[c0 + t] + lnb[c0 + t];
        if (nn < NN) {
#pragma unroll
            for (int t4 = 0; t4 < 8; t4++) {
                *(float4*)&g_h[nn * HID + c0 + t4 * 4] =
                    make_float4(o[t4 * 4], o[t4 * 4 + 1], o[t4 * 4 + 2], o[t4 * 4 + 3]);
                u32 h0, l0, h1, l1;
                split2(o[t4 * 4], o[t4 * 4 + 1], h0, l0);
                split2(o[t4 * 4 + 2], o[t4 * 4 + 3], h1, l1);
                *(u32*)&g_hh[nn * HID + c0 + t4 * 4]     = h0;
                *(u32*)&g_hh[nn * HID + c0 + t4 * 4 + 2] = h1;
                *(u32*)&g_hl[nn * HID + c0 + t4 * 4]     = l0;
                *(u32*)&g_hl[nn * HID + c0 + t4 * 4 + 2] = l1;
            }
        }
        if (do_pre) {
#pragma unroll
            for (int t = 0; t < 16; t++) {
                u32 h, l;
                split2(o[2 * t], o[2 * t + 1], h, l);
                *(u32*)&sAh[ln * UPP + c0 + 2 * t] = h;
                *(u32*)&sAl[ln * UPP + c0 + 2 * t] = l;
            }
        }
    }

    // ---- fused next-layer node_pre ----
    if (do_pre) {
        __syncthreads();
        int npl = layer + 1;
        for (int half = 0; half < 2; half++) {
            const u16* wh = g_NPh + npl * 256 * 128 + half * 128 * 128;
            const u16* wl = g_NPl + npl * 256 * 128 + half * 128 * 128;
            for (int idx = tid; idx < 128 * 16; idx += 256) {
                int r = idx >> 4, c = (idx & 15) * 8;
                *(uint4*)&sWh[r * UPP + c] = *(const uint4*)&wh[r * 128 + c];
                *(uint4*)&sWl[r * UPP + c] = *(const uint4*)&wl[r * 128 + c];
            }
            __syncthreads();
            float accp[2][4][4];
#pragma unroll
            for (int i = 0; i < 2; i++)
#pragma unroll
                for (int j = 0; j < 4; j++)
#pragma unroll
                    for (int k = 0; k < 4; k++) accp[i][j][k] = 0.f;
            for (int ks = 0; ks < 8; ks++) {
                int kb = ks * 16;
                u32 ah[2][4], al[2][4];
#pragma unroll
                for (int mt = 0; mt < 2; mt++) {
                    int r = m0 + mt * 16 + (lane & 15);
                    int c = kb + ((lane >> 4) << 3);
                    u32 off = (u32)(r * UPP + c) * 2;
                    ldsm4(ah[mt], sb + U_AH + off);
                    ldsm4(al[mt], sb + U_AL + off);
                }
#pragma unroll
                for (int nt = 0; nt < 4; nt++) {
                    int rn = nw0 + nt * 8 + (lane & 7);
                    int cn = kb + (((lane >> 3) & 1) << 3);
                    u32 offb = (u32)(rn * UPP + cn) * 2;
                    u32 bh[2], bl[2];
                    ldsm2(bh, sb + U_WH + offb);
                    ldsm2(bl, sb + U_WL + offb);
#pragma unroll
                    for (int mt = 0; mt < 2; mt++) {
                        mma16816(accp[mt][nt], ah[mt], bh);
                        mma16816(accp[mt][nt], ah[mt], bl);
                        mma16816(accp[mt][nt], al[mt], bh);
                    }
                }
            }
#pragma unroll
            for (int mt = 0; mt < 2; mt++)
#pragma unroll
                for (int nt = 0; nt < 4; nt++) {
                    int rA = m0 + mt * 16 + (lane >> 2);
                    int rB = rA + 8;
                    int c = half * 128 + nw0 + nt * 8 + 2 * (lane & 3);
                    int nA = n0 + rA, nB = n0 + rB;
                    if (nA < NN) {
                        g_pre[(u64)nA * 256 + c]     = accp[mt][nt][0];
                        g_pre[(u64)nA * 256 + c + 1] = accp[mt][nt][1];
                    }
                    if (nB < NN) {
                        g_pre[(u64)nB * 256 + c]     = accp[mt][nt][2];
                        g_pre[(u64)nB * 256 + c + 1] = accp[mt][nt][3];
                    }
                }
            __syncthreads();
        }
    }
}

// ---------------- final readout ----------------
__global__ void k_final(const float* __restrict__ gc,
                        const float* __restrict__ qw1,
                        const float* __restrict__ qb1,
                        const float* __restrict__ qw2,
                        const float* __restrict__ qb2p,
                        float* __restrict__ out) {
    __shared__ float sA[32 * 33];
    __shared__ float sW[128 * 33];
    __shared__ float sctx[64];
    __shared__ float sout[32];
    int tid = threadIdx.x;
    int n0 = blockIdx.x * 32;
    if (tid < 64) sctx[tid] = gc[tid];
    if (tid < 32) sout[tid] = qb2p[0];
    __syncthreads();
    int tc = tid & 31, trg = tid >> 5;
    float acc[4][4] = {};
    for (int kb = 0; kb < 192; kb += 32) {
        for (int idx = tid; idx < 32 * 32; idx += NT) {
            int r = idx >> 5, kk = idx & 31;
            int n = n0 + r;
            int kg = kb + kk;
            float v = 0.f;
            if (n < NN) v = (kg < 128) ? g_h[n * HID + kg] : sctx[kg - 128];
            sA[r * 33 + kk] = v;
        }
        for (int idx = tid; idx < 128 * 32; idx += NT) {
            int o = idx >> 5, kk = idx & 31;
            sW[o * 33 + kk] = qw1[o * 192 + kb + kk];
        }
        __syncthreads();
#pragma unroll 8
        for (int k = 0; k < 32; k++) {
            float a[4], w[4];
#pragma unroll
            for (int i = 0; i < 4; i++) a[i] = sA[(trg * 4 + i) * 33 + k];
#pragma unroll
            for (int j = 0; j < 4; j++) w[j] = sW[(tc + 32 * j) * 33 + k];
#pragma unroll
            for (int i = 0; i < 4; i++)
#pragma unroll
                for (int j = 0; j < 4; j++) acc[i][j] += a[i] * w[j];
        }
        __syncthreads();
    }
    float p[4] = {0.f, 0.f, 0.f, 0.f};
#pragma unroll
    for (int j = 0; j < 4; j++) {
        int c = tc + 32 * j;
        float b = qb1[c], w2 = qw2[c];
#pragma unroll
        for (int i = 0; i < 4; i++) {
            float v = fmaxf(acc[i][j] + b, 0.f);
            p[i] += v * w2;
        }
    }
#pragma unroll
    for (int i = 0; i < 4; i++) atomicAdd(&sout[trg * 4 + i], p[i]);
    __syncthreads();
    if (tid < 32) {
        int n = n0 + tid;
        if (n < NN) out[n] = sout[tid];
    }
}

// ---------------- launch ----------------
extern "C" void kernel_launch(void* const* d_in, const int* in_sizes, int n_in,
                              void* d_out, int out_size) {
    const float* x    = (const float*)d_in[0];
    const void*  eidx = d_in[1];
    const float* ea   = (const float*)d_in[2];
    const float* gc   = (const float*)d_in[3];
    const float* npw  = (const float*)d_in[4];
    const float* npb  = (const float*)d_in[5];
    const float* mw1  = (const float*)d_in[6];
    const float* mb1  = (const float*)d_in[7];
    const float* mw2  = (const float*)d_in[8];
    const float* mb2  = (const float*)d_in[9];
    const float* aw1  = (const float*)d_in[10];
    const float* ab1  = (const float*)d_in[11];
    const float* aw2  = (const float*)d_in[12];
    const float* ab2  = (const float*)d_in[13];
    const float* uw1  = (const float*)d_in[14];
    const float* ub1  = (const float*)d_in[15];
    const float* uw2  = (const float*)d_in[16];
    const float* ub2  = (const float*)d_in[17];
    const float* lng  = (const float*)d_in[18];
    const float* lnb  = (const float*)d_in[19];
    const float* qw1  = (const float*)d_in[20];
    const float* qb1  = (const float*)d_in[21];
    const float* qw2  = (const float*)d_in[22];
    const float* qb2  = (const float*)d_in[23];
    float* out = (float*)d_out;

    cudaFuncSetAttribute(k_msg, cudaFuncAttributeMaxDynamicSharedMemorySize, SMEM_MSG2);
    cudaFuncSetAttribute(k_node_pre, cudaFuncAttributeMaxDynamicSharedMemorySize, SMEM_NP);
    cudaFuncSetAttribute(k_update, cudaFuncAttributeMaxDynamicSharedMemorySize, SMEM_UPD);

    int prep_tot = 3 * (256 * 128 + 192 * 16 + 128 * 128 + 256 * 128 + 128 * 128);
    k_prep<<<(prep_tot + 255) / 256, 256>>>(mw1, mw2, aw1, uw1, uw2);
    k_detect<<<1, NT>>>((const unsigned*)eidx);
    k_convert<<<(NE + NT - 1) / NT, NT>>>(eidx, ea);
    k_hist<<<(NE + 255) / 256, 256>>>();
    k_scan<<<1, 1024>>>();
    k_scatter<<<(NE + 255) / 256, 256>>>();
    k_nodeproj<<<(NN + 31) / 32, NT>>>(x, npw, npb);

    int ngrid = (NN + 63) / 64;
    k_node_pre<<<ngrid, 256, SMEM_NP>>>(0);
    for (int l = 0; l < 3; l++) {
        k_attn_lite<<<(NE + 63) / 64, 256>>>(ea, aw1 + l * 64 * 272, ab1 + l * 64,
                                             aw2 + l * 64, ab2 + l, l);
        k_exp<<<(NE + NT - 1) / NT, NT>>>(l);
        k_msg<<<296, 256, SMEM_MSG2>>>(mb1 + l * 128, mb2 + l * 128, l);
        k_update<<<ngrid, 256, SMEM_UPD>>>(ub1 + l * 128, ub2 + l * 128,
                                           lng + l * 128, lnb + l * 128, l,
                                           (l < 2) ? 1 : 0);
    }
    k_final<<<(NN + 31) / 32, NT>>>(gc, qw1, qb1, qw2, qb2, out);
}

// round 16
// speedup vs baseline: 1.1161x; 1.0136x over previous
#include <cuda_runtime.h>
#include <cuda_bf16.h>

#define NN 50000
#define NE 600000
#define HID 128
#define NT 256

typedef unsigned long long u64;
typedef unsigned int u32;
typedef unsigned short u16;

// ---------------- scratch ----------------
__device__ float g_h[NN * HID];
__device__ float g_pre[NN * 256];      // [0:64)=u_s, [64:128)=u_d, [128:256)=vh
__device__ float g_msgbuf[(u64)NE * 128];
__device__ float g_sumexp[3 * NN];
__device__ float g_scores[NE];
__device__ float g_es[NE];
__device__ int   g_src[NE];
__device__ int   g_dst[NE];
__device__ unsigned g_maxenc[3];
__device__ int   g_is64;
// CSR by dst
__device__ int g_cnt[NN];
__device__ int g_row[NN];
__device__ int g_cur[NN];
__device__ int g_eord[NE];
// bf16 hi/lo splits
__device__ __align__(16) u16 g_hh[NN * HID];
__device__ __align__(16) u16 g_hl[NN * HID];
__device__ __align__(16) u16 g_eah[NE * 16];
__device__ __align__(16) u16 g_eal[NE * 16];
__device__ __align__(16) u16 g_NPh[3 * 256 * 128];
__device__ __align__(16) u16 g_NPl[3 * 256 * 128];
__device__ __align__(16) u16 g_EWh[3 * 192 * 16];
__device__ __align__(16) u16 g_EWl[3 * 192 * 16];
__device__ __align__(16) u16 g_W2h[3 * 128 * 128];
__device__ __align__(16) u16 g_W2l[3 * 128 * 128];
__device__ __align__(16) u16 g_U1h[3 * 256 * 128];
__device__ __align__(16) u16 g_U1l[3 * 256 * 128];
__device__ __align__(16) u16 g_U2h[3 * 128 * 128];
__device__ __align__(16) u16 g_U2l[3 * 128 * 128];

__device__ __forceinline__ unsigned fenc(float f) {
    unsigned u = __float_as_uint(f);
    return (u & 0x80000000u) ? ~u : (u | 0x80000000u);
}
__device__ __forceinline__ float fdec(unsigned u) {
    return (u & 0x80000000u) ? __uint_as_float(u & 0x7fffffffu)
                             : __uint_as_float(~u);
}

// ---------------- streaming mem helpers ----------------
__device__ __forceinline__ void stcs_f2(float* p, float2 v) {
    asm volatile("st.global.cs.v2.f32 [%0], {%1, %2};"
                 :: "l"(p), "f"(v.x), "f"(v.y) : "memory");
}
__device__ __forceinline__ float4 ldcs_f4(const float* p) {
    float4 v;
    asm volatile("ld.global.cs.v4.f32 {%0, %1, %2, %3}, [%4];"
                 : "=f"(v.x), "=f"(v.y), "=f"(v.z), "=f"(v.w) : "l"(p));
    return v;
}

// ---------------- bf16 split helpers ----------------
__device__ __forceinline__ void split_bf16(float v, u16 &h, u16 &l) {
    __nv_bfloat16 bh = __float2bfloat16(v);
    __nv_bfloat16 bl = __float2bfloat16(v - __bfloat162float(bh));
    h = __bfloat16_as_ushort(bh);
    l = __bfloat16_as_ushort(bl);
}
__device__ __forceinline__ void split2(float a, float b, u32 &h, u32 &l) {
    u16 h0, l0, h1, l1;
    split_bf16(a, h0, l0);
    split_bf16(b, h1, l1);
    h = (u32)h0 | ((u32)h1 << 16);
    l = (u32)l0 | ((u32)l1 << 16);
}

// ---------------- HMMA helpers ----------------
__device__ __forceinline__ u32 smem_u32(const void* p) {
    u32 a;
    asm("{ .reg .u64 t; cvta.to.shared.u64 t, %1; cvt.u32.u64 %0, t; }"
        : "=r"(a) : "l"(p));
    return a;
}
__device__ __forceinline__ void ldsm4(u32* r, u32 addr) {
    asm volatile("ldmatrix.sync.aligned.m8n8.x4.shared.b16 {%0,%1,%2,%3}, [%4];"
        : "=r"(r[0]), "=r"(r[1]), "=r"(r[2]), "=r"(r[3]) : "r"(addr));
}
__device__ __forceinline__ void ldsm2(u32* r, u32 addr) {
    asm volatile("ldmatrix.sync.aligned.m8n8.x2.shared.b16 {%0,%1}, [%2];"
        : "=r"(r[0]), "=r"(r[1]) : "r"(addr));
}
__device__ __forceinline__ void mma16816(float* d, const u32* a, const u32* b) {
    asm volatile("mma.sync.aligned.m16n8k16.row.col.f32.bf16.bf16.f32 "
        "{%0,%1,%2,%3}, {%4,%5,%6,%7}, {%8,%9}, {%0,%1,%2,%3};"
        : "+f"(d[0]), "+f"(d[1]), "+f"(d[2]), "+f"(d[3])
        : "r"(a[0]), "r"(a[1]), "r"(a[2]), "r"(a[3]), "r"(b[0]), "r"(b[1]));
}

// ---------------- weight preconversion ----------------
__global__ void k_prep(const float* __restrict__ mw1, const float* __restrict__ mw2,
                       const float* __restrict__ aw1, const float* __restrict__ uw1,
                       const float* __restrict__ uw2) {
    int idx = blockIdx.x * blockDim.x + threadIdx.x;
    const int NP = 3 * 256 * 128, EW = 3 * 192 * 16, W2 = 3 * 128 * 128;
    const int U1 = 3 * 256 * 128, U2 = 3 * 128 * 128;
    u16 h, l;
    if (idx < NP) {
        int lyr = idx / (256 * 128);
        int rem = idx % (256 * 128);
        int n = rem / 128, k = rem % 128;
        float v;
        if (n < 64)        v = aw1[lyr * 64 * 272 + n * 272 + k];
        else if (n < 128)  v = aw1[lyr * 64 * 272 + (n - 64) * 272 + 128 + k];
        else               v = mw1[lyr * 128 * 144 + (n - 128) * 144 + k];
        split_bf16(v, h, l);
        g_NPh[idx] = h; g_NPl[idx] = l;
    } else if (idx < NP + EW) {
        int i = idx - NP;
        int lyr = i / (192 * 16);
        int rem = i % (192 * 16);
        int n = rem / 16, k = rem % 16;
        float v = (n < 64) ? aw1[lyr * 64 * 272 + n * 272 + 256 + k]
                           : mw1[lyr * 128 * 144 + (n - 64) * 144 + 128 + k];
        split_bf16(v, h, l);
        g_EWh[i] = h; g_EWl[i] = l;
    } else if (idx < NP + EW + W2) {
        int i = idx - NP - EW;
        split_bf16(mw2[i], h, l);
        g_W2h[i] = h; g_W2l[i] = l;
    } else if (idx < NP + EW + W2 + U1) {
        int i = idx - NP - EW - W2;
        int lyr = i / 32768;
        int rem = i % 32768;
        int half = rem / 16384;
        int r2 = rem % 16384;
        int n = r2 / 128, k = r2 % 128;
        split_bf16(uw1[lyr * 32768 + n * 256 + half * 128 + k], h, l);
        g_U1h[i] = h; g_U1l[i] = l;
    } else if (idx < NP + EW + W2 + U1 + U2) {
        int i = idx - NP - EW - W2 - U1;
        split_bf16(uw2[i], h, l);
        g_U2h[i] = h; g_U2l[i] = l;
    }
}

// ---------------- detect + convert + ea split + zero ----------------
__global__ void k_detect(const unsigned* __restrict__ raw) {
    __shared__ int nz;
    if (threadIdx.x == 0) nz = 0;
    __syncthreads();
    for (int i = threadIdx.x; i < 2048; i += NT)
        if (raw[2 * i + 1] != 0u) atomicOr(&nz, 1);
    __syncthreads();
    if (threadIdx.x == 0) g_is64 = (nz == 0) ? 1 : 0;
}

__global__ void k_convert(const void* __restrict__ eidx, const float* __restrict__ ea) {
    int i = blockIdx.x * blockDim.x + threadIdx.x;
    long long stride = (long long)gridDim.x * blockDim.x;
    if (i < NE) {
        if (g_is64) {
            const long long* p = (const long long*)eidx;
            g_src[i] = (int)p[i];
            g_dst[i] = (int)p[NE + i];
        } else {
            const int* p = (const int*)eidx;
            g_src[i] = p[i];
            g_dst[i] = p[NE + i];
        }
    }
    for (long long j = i; j < (long long)NE * 16; j += stride) {
        u16 h, l;
        split_bf16(ea[j], h, l);
        g_eah[j] = h; g_eal[j] = l;
    }
    for (long long j = i; j < 3 * NN; j += stride) g_sumexp[j] = 0.f;
    for (long long j = i; j < NN; j += stride) g_cnt[j] = 0;
    if (i == 0) {
        g_maxenc[0] = 0x007FFFFFu;
        g_maxenc[1] = 0x007FFFFFu;
        g_maxenc[2] = 0x007FFFFFu;
    }
}

// ---------------- counting sort by dst (CSR) ----------------
__global__ void k_hist() {
    int i = blockIdx.x * blockDim.x + threadIdx.x;
    if (i < NE) atomicAdd(&g_cnt[g_dst[i]], 1);
}

__global__ void k_scan() {
    __shared__ int warpsum[32];
    __shared__ int scarry;
    int tid = threadIdx.x, lane = tid & 31, wid = tid >> 5;
    if (tid == 0) scarry = 0;
    __syncthreads();
    for (int base = 0; base < NN; base += 1024) {
        int i = base + tid;
        int v = (i < NN) ? g_cnt[i] : 0;
        int s = v;
#pragma unroll
        for (int off = 1; off < 32; off <<= 1) {
            int t = __shfl_up_sync(0xffffffffu, s, off);
            if (lane >= off) s += t;
        }
        if (lane == 31) warpsum[wid] = s;
        __syncthreads();
        if (wid == 0) {
            int ws = warpsum[lane];
#pragma unroll
            for (int off = 1; off < 32; off <<= 1) {
                int t = __shfl_up_sync(0xffffffffu, ws, off);
                if (lane >= off) ws += t;
            }
            warpsum[lane] = ws;
        }
        __syncthreads();
        int incl = s + (wid > 0 ? warpsum[wid - 1] : 0) + scarry;
        if (i < NN) { g_row[i] = incl - v; g_cur[i] = incl - v; }
        __syncthreads();
        if (tid == 1023) scarry = incl;
        __syncthreads();
    }
}

__global__ void k_scatter() {
    int i = blockIdx.x * blockDim.x + threadIdx.x;
    if (i < NE) {
        int pos = atomicAdd(&g_cur[g_dst[i]], 1);
        g_eord[pos] = i;
    }
}

// ---------------- node projection (+ split store) ----------------
__global__ void k_nodeproj(const float* __restrict__ x,
                           const float* __restrict__ W,
                           const float* __restrict__ b) {
    __shared__ float sA[32 * 33];
    __shared__ float sW[128 * 33];
    int tid = threadIdx.x;
    int n0 = blockIdx.x * 32;
    for (int idx = tid; idx < 32 * 32; idx += NT) {
        int r = idx >> 5, k = idx & 31;
        int n = n0 + r;
        sA[r * 33 + k] = (n < NN) ? x[n * 32 + k] : 0.f;
    }
    for (int idx = tid; idx < 128 * 32; idx += NT) {
        int o = idx >> 5, k = idx & 31;
        sW[o * 33 + k] = W[o * 32 + k];
    }
    __syncthreads();
    int tc = tid & 31, trg = tid >> 5;
    float acc[4][4] = {};
#pragma unroll 8
    for (int k = 0; k < 32; k++) {
        float a[4], w[4];
#pragma unroll
        for (int i = 0; i < 4; i++) a[i] = sA[(trg * 4 + i) * 33 + k];
#pragma unroll
        for (int j = 0; j < 4; j++) w[j] = sW[(tc + 32 * j) * 33 + k];
#pragma unroll
        for (int i = 0; i < 4; i++)
#pragma unroll
            for (int j = 0; j < 4; j++) acc[i][j] += a[i] * w[j];
    }
#pragma unroll
    for (int i = 0; i < 4; i++) {
        int n = n0 + trg * 4 + i;
        if (n < NN)
#pragma unroll
            for (int j = 0; j < 4; j++) {
                int c = tc + 32 * j;
                float v = fmaxf(acc[i][j] + b[c], 0.f);
                g_h[n * HID + c] = v;
                u16 h, l;
                split_bf16(v, h, l);
                g_hh[n * HID + c] = h;
                g_hl[n * HID + c] = l;
            }
    }
}

// ---------------- node precompute GEMM: M=64 tiles, 2 CTAs/SM (layer 0 only) ----------------
#define NPP 136
#define NP_AH 0
#define NP_AL 17408
#define NP_WH 34816
#define NP_WL 69632
#define SMEM_NP 104448

__global__ void __launch_bounds__(256, 2)
k_node_pre(int layer) {
    extern __shared__ char sm[];
    u16* sAh = (u16*)(sm + NP_AH);
    u16* sAl = (u16*)(sm + NP_AL);
    u16* sWh = (u16*)(sm + NP_WH);
    u16* sWl = (u16*)(sm + NP_WL);
    u32 sb = smem_u32(sm);
    int tid = threadIdx.x, lane = tid & 31, w = tid >> 5;
    int n0 = blockIdx.x * 64;

    for (int idx = tid; idx < 64 * 16; idx += 256) {
        int r = idx >> 4, c = (idx & 15) * 8;
        int n = n0 + r;
        if (n < NN) {
            *(uint4*)&sAh[r * NPP + c] = *(const uint4*)&g_hh[n * HID + c];
            *(uint4*)&sAl[r * NPP + c] = *(const uint4*)&g_hl[n * HID + c];
        } else {
            uint4 z = make_uint4(0, 0, 0, 0);
            *(uint4*)&sAh[r * NPP + c] = z;
            *(uint4*)&sAl[r * NPP + c] = z;
        }
    }

    int m0 = (w & 1) * 32, n0w = (w >> 1) * 32;
    for (int half = 0; half < 2; half++) {
        const u16* wh = g_NPh + layer * 256 * 128 + half * 128 * 128;
        const u16* wl = g_NPl + layer * 256 * 128 + half * 128 * 128;
        for (int idx = tid; idx < 128 * 16; idx += 256) {
            int r = idx >> 4, c = (idx & 15) * 8;
            *(uint4*)&sWh[r * NPP + c] = *(const uint4*)&wh[r * 128 + c];
            *(uint4*)&sWl[r * NPP + c] = *(const uint4*)&wl[r * 128 + c];
        }
        __syncthreads();
        float acc[2][4][4];
#pragma unroll
        for (int i = 0; i < 2; i++)
#pragma unroll
            for (int j = 0; j < 4; j++)
#pragma unroll
                for (int k = 0; k < 4; k++) acc[i][j][k] = 0.f;
        for (int ks = 0; ks < 8; ks++) {
            int kb = ks * 16;
            u32 ah[2][4], al[2][4];
#pragma unroll
            for (int mt = 0; mt < 2; mt++) {
                int r = m0 + mt * 16 + (lane & 15);
                int c = kb + ((lane >> 4) << 3);
                u32 off = (u32)(r * NPP + c) * 2;
                ldsm4(ah[mt], sb + NP_AH + off);
                ldsm4(al[mt], sb + NP_AL + off);
            }
#pragma unroll
            for (int nt = 0; nt < 4; nt++) {
                int rn = n0w + nt * 8 + (lane & 7);
                int cn = kb + (((lane >> 3) & 1) << 3);
                u32 offb = (u32)(rn * NPP + cn) * 2;
                u32 bh[2], bl[2];
                ldsm2(bh, sb + NP_WH + offb);
                ldsm2(bl, sb + NP_WL + offb);
#pragma unroll
                for (int mt = 0; mt < 2; mt++) {
                    mma16816(acc[mt][nt], ah[mt], bh);
                    mma16816(acc[mt][nt], ah[mt], bl);
                    mma16816(acc[mt][nt], al[mt], bh);
                }
            }
        }
#pragma unroll
        for (int mt = 0; mt < 2; mt++)
#pragma unroll
            for (int nt = 0; nt < 4; nt++) {
                int rA = m0 + mt * 16 + (lane >> 2);
                int rB = rA + 8;
                int c = half * 128 + n0w + nt * 8 + 2 * (lane & 3);
                int nA = n0 + rA, nB = n0 + rB;
                if (nA < NN) {
                    g_pre[(u64)nA * 256 + c]     = acc[mt][nt][0];
                    g_pre[(u64)nA * 256 + c + 1] = acc[mt][nt][1];
                }
                if (nB < NN) {
                    g_pre[(u64)nB * 256 + c]     = acc[mt][nt][2];
                    g_pre[(u64)nB * 256 + c + 1] = acc[mt][nt][3];
                }
            }
        __syncthreads();
    }
}

// ---------------- attention scores (elementwise, decomposed) ----------------
__global__ void __launch_bounds__(256, 4)
k_attn_lite(const float* __restrict__ ea,
            const float* __restrict__ aw1l,
            const float* __restrict__ ab1,
            const float* __restrict__ aw2,
            const float* __restrict__ ab2p, int layer) {
    __shared__ float sea[64 * 17];
    __shared__ float sW[64 * 16];
    __shared__ float sb1[64], sv[64];
    __shared__ unsigned smax;
    int tid = threadIdx.x;
    int e0 = blockIdx.x * 64;
    if (tid == 0) smax = 0x007FFFFFu;
    {
        int r = tid >> 2, c = (tid & 3) * 4;
        float4 v = make_float4(0.f, 0.f, 0.f, 0.f);
        if (e0 + r < NE) v = *(const float4*)&ea[(u64)(e0 + r) * 16 + c];
        sea[r * 17 + c]     = v.x;
        sea[r * 17 + c + 1] = v.y;
        sea[r * 17 + c + 2] = v.z;
        sea[r * 17 + c + 3] = v.w;
    }
    {
        int r = tid >> 2, c = (tid & 3) * 4;
        float4 wv = *(const float4*)&aw1l[r * 272 + 256 + c];
        *(float4*)&sW[r * 16 + c] = wv;
    }
    if (tid < 64) { sb1[tid] = ab1[tid]; sv[tid] = aw2[tid]; }
    __syncthreads();

    int el = tid >> 2, p = tid & 3;
    int e = e0 + el;
    float score = 0.f;
    if (e < NE) {
        int s = g_src[e], d = g_dst[e];
        const float* ps = &g_pre[(u64)s * 256 + p * 16];
        const float* pd = &g_pre[(u64)d * 256 + 64 + p * 16];
        const float* er = &sea[el * 17];
#pragma unroll
        for (int c4 = 0; c4 < 4; c4++) {
            float4 a4 = *(const float4*)&ps[c4 * 4];
            float4 b4 = *(const float4*)&pd[c4 * 4];
            float av[4] = {a4.x, a4.y, a4.z, a4.w};
            float bv[4] = {b4.x, b4.y, b4.z, b4.w};
#pragma unroll
            for (int j = 0; j < 4; j++) {
                int c = p * 16 + c4 * 4 + j;
                float x = av[j] + bv[j] + sb1[c];
                const float* wr = &sW[c * 16];
#pragma unroll
                for (int k = 0; k < 16; k++) x += er[k] * wr[k];
                x = (x > 0.f) ? x : 0.2f * x;
                score += x * sv[c];
            }
        }
    }
    score += __shfl_xor_sync(0xffffffffu, score, 1);
    score += __shfl_xor_sync(0xffffffffu, score, 2);
    if (p == 0 && e < NE) {
        float sc = score + ab2p[0];
        g_scores[e] = sc;
        atomicMax(&smax, fenc(sc));
    }
    __syncthreads();
    if (tid == 0) atomicMax(&g_maxenc[layer], smax);
}

// ---------------- exp + scatter sum ----------------
__global__ void k_exp(int layer) {
    int i = blockIdx.x * blockDim.x + threadIdx.x;
    if (i >= NE) return;
    float m = fdec(g_maxenc[layer]);
    float es = __expf(g_scores[i] - m);
    g_es[i] = es;
    atomicAdd(&g_sumexp[layer * NN + g_dst[i]], es);
}

// ---------------- message MLP: persistent weights, grid-stride tiles, prefetch ----------------
#define AP2 136
#define M_AH 0
#define M_AL 17408
#define M_WH 34816
#define M_WL 69632
#define M_META 104448
#define SMEM_MSG2 (104448 + 1536)
#define NTILES ((NE + 63) / 64)
#define MSG_GRID 304

__global__ void __launch_bounds__(256, 2)
k_msg(const float* __restrict__ mb1,
      const float* __restrict__ mb2, int layer) {
    extern __shared__ char sm[];
    u16* sAh = (u16*)(sm + M_AH);
    u16* sAl = (u16*)(sm + M_AL);
    u16* sWh = (u16*)(sm + M_WH);
    u16* sWl = (u16*)(sm + M_WL);
    int*   ssrc = (int*)(sm + M_META);
    float* swt  = (float*)(sm + M_META + 256);
    float* smb1 = (float*)(sm + M_META + 512);
    float* smb2 = (float*)(sm + M_META + 1024);
    u32 sb = smem_u32(sm);

    int tid = threadIdx.x, lane = tid & 31, w = tid >> 5;
    int m0 = (w & 1) * 32, n0 = (w >> 1) * 32;

    // ---- one-time setup: stage Wea (compact stride 16) in A area, load W2, biases ----
    {
        const u16* wh = g_EWh + layer * 192 * 16 + 64 * 16;
        const u16* wl = g_EWl + layer * 192 * 16 + 64 * 16;
        for (int idx = tid; idx < 128 * 2; idx += 256) {
            int r = idx >> 1, c = (idx & 1) * 8;
            *(uint4*)&sAh[r * 16 + c] = *(const uint4*)&wh[r * 16 + c];
            *(uint4*)&sAl[r * 16 + c] = *(const uint4*)&wl[r * 16 + c];
        }
        const u16* w2h = g_W2h + layer * 128 * 128;
        const u16* w2l = g_W2l + layer * 128 * 128;
        for (int idx = tid; idx < 128 * 16; idx += 256) {
            int r = idx >> 4, c = (idx & 15) * 8;
            *(uint4*)&sWh[r * AP2 + c] = *(const uint4*)&w2h[r * 128 + c];
            *(uint4*)&sWl[r * AP2 + c] = *(const uint4*)&w2l[r * 128 + c];
        }
        if (tid < 128) { smb1[tid] = mb1[tid]; smb2[tid] = mb2[tid]; }
    }
    __syncthreads();
    // Wea fragments -> registers (held across all tiles)
    u32 weah[4][2], weal[4][2];
#pragma unroll
    for (int nt = 0; nt < 4; nt++) {
        int rn = n0 + nt * 8 + (lane & 7);
        int cn = ((lane >> 3) & 1) << 3;
        u32 off = (u32)(rn * 16 + cn) * 2;
        ldsm2(weah[nt], sb + M_AH + off);
        ldsm2(weal[nt], sb + M_AL + off);
    }
    __syncthreads();

    // ---- register prefetch state for next tile ----
    uint4 pf_eah = make_uint4(0, 0, 0, 0), pf_eal = make_uint4(0, 0, 0, 0);
    int pf_src = 0;
    float pf_wt = 0.f;

    // prologue: prefetch first tile
    {
        int tt = blockIdx.x;
        if (tt < NTILES) {
            int e0p = tt * 64;
            if (tid < 64) {
                int e = e0p + tid;
                if (e < NE) {
                    pf_src = g_src[e];
                    int d = g_dst[e];
                    pf_wt = g_es[e] / (g_sumexp[layer * NN + d] + 1e-6f);
                } else { pf_src = 0; pf_wt = 0.f; }
            }
            if (tid < 128) {
                int r = tid >> 1, c = (tid & 1) * 8;
                int e = min(e0p + r, NE - 1);
                pf_eah = *(const uint4*)&g_eah[(u64)e * 16 + c];
                pf_eal = *(const uint4*)&g_eal[(u64)e * 16 + c];
            }
        }
    }

    for (int t = blockIdx.x; t < NTILES; t += gridDim.x) {
        int e0 = t * 64;
        // store prefetched meta + ea to smem
        if (tid < 64) { ssrc[tid] = pf_src; swt[tid] = pf_wt; }
        if (tid < 128) {
            int r = tid >> 1, c = (tid & 1) * 8;
            *(uint4*)&sAh[r * AP2 + c] = pf_eah;
            *(uint4*)&sAl[r * AP2 + c] = pf_eal;
        }
        __syncthreads();

        // prefetch NEXT tile (loads overlap the GEMMs below)
        {
            int tt = t + gridDim.x;
            if (tt < NTILES) {
                int e0p = tt * 64;
                if (tid < 64) {
                    int e = e0p + tid;
                    if (e < NE) {
                        pf_src = g_src[e];
                        int d = g_dst[e];
                        pf_wt = g_es[e] / (g_sumexp[layer * NN + d] + 1e-6f);
                    } else { pf_src = 0; pf_wt = 0.f; }
                }
                if (tid < 128) {
                    int r = tid >> 1, c = (tid & 1) * 8;
                    int e = min(e0p + r, NE - 1);
                    pf_eah = *(const uint4*)&g_eah[(u64)e * 16 + c];
                    pf_eal = *(const uint4*)&g_eal[(u64)e * 16 + c];
                }
            }
        }

        // GEMM_ea: K=16, Wea from registers
        float acc[2][4][4];
#pragma unroll
        for (int i = 0; i < 2; i++)
#pragma unroll
            for (int j = 0; j < 4; j++)
#pragma unroll
                for (int k = 0; k < 4; k++) acc[i][j][k] = 0.f;
        {
            u32 ah[2][4], al[2][4];
#pragma unroll
            for (int mt = 0; mt < 2; mt++) {
                int r = m0 + mt * 16 + (lane & 15);
                int c = (lane >> 4) << 3;
                u32 off = (u32)(r * AP2 + c) * 2;
                ldsm4(ah[mt], sb + M_AH + off);
                ldsm4(al[mt], sb + M_AL + off);
            }
#pragma unroll
            for (int nt = 0; nt < 4; nt++) {
#pragma unroll
                for (int mt = 0; mt < 2; mt++) {
                    mma16816(acc[mt][nt], ah[mt], weah[nt]);
                    mma16816(acc[mt][nt], ah[mt], weal[nt]);
                    mma16816(acc[mt][nt], al[mt], weah[nt]);
                }
            }
        }
        __syncthreads();

        // epilogue-ea: m = relu(eaW + vh + b1) -> split into A tiles (vh direct from L2)
#pragma unroll
        for (int mt = 0; mt < 2; mt++)
#pragma unroll
            for (int nt = 0; nt < 4; nt++) {
                int rA = m0 + mt * 16 + (lane >> 2);
                int rB = rA + 8;
                int c = n0 + nt * 8 + 2 * (lane & 3);
                float b0 = smb1[c], b1 = smb1[c + 1];
                float2 vA = *(const float2*)&g_pre[(u64)ssrc[rA] * 256 + 128 + c];
                float2 vB = *(const float2*)&g_pre[(u64)ssrc[rB] * 256 + 128 + c];
                u32 h, l;
                split2(fmaxf(acc[mt][nt][0] + vA.x + b0, 0.f),
                       fmaxf(acc[mt][nt][1] + vA.y + b1, 0.f), h, l);
                *(u32*)&sAh[rA * AP2 + c] = h;
                *(u32*)&sAl[rA * AP2 + c] = l;
                split2(fmaxf(acc[mt][nt][2] + vB.x + b0, 0.f),
                       fmaxf(acc[mt][nt][3] + vB.y + b1, 0.f), h, l);
                *(u32*)&sAh[rB * AP2 + c] = h;
                *(u32*)&sAl[rB * AP2 + c] = l;
            }
        __syncthreads();

        // GEMM2 K=128 (W2 resident)
        float acc2[2][4][4];
#pragma unroll
        for (int i = 0; i < 2; i++)
#pragma unroll
            for (int j = 0; j < 4; j++)
#pragma unroll
                for (int k = 0; k < 4; k++) acc2[i][j][k] = 0.f;

        for (int ks = 0; ks < 8; ks++) {
            int kb = ks * 16;
            u32 ah[2][4], al[2][4];
#pragma unroll
            for (int mt = 0; mt < 2; mt++) {
                int r = m0 + mt * 16 + (lane & 15);
                int c = kb + ((lane >> 4) << 3);
                u32 off = (u32)(r * AP2 + c) * 2;
                ldsm4(ah[mt], sb + M_AH + off);
                ldsm4(al[mt], sb + M_AL + off);
            }
#pragma unroll
            for (int nt = 0; nt < 4; nt++) {
                int rn = n0 + nt * 8 + (lane & 7);
                int cn = kb + (((lane >> 3) & 1) << 3);
                u32 offb = (u32)(rn * AP2 + cn) * 2;
                u32 bh[2], bl[2];
                ldsm2(bh, sb + M_WH + offb);
                ldsm2(bl, sb + M_WL + offb);
#pragma unroll
                for (int mt = 0; mt < 2; mt++) {
                    mma16816(acc2[mt][nt], ah[mt], bh);
                    mma16816(acc2[mt][nt], ah[mt], bl);
                    mma16816(acc2[mt][nt], al[mt], bh);
                }
            }
        }

        // epilogue2: weighted message -> streaming store to g_msgbuf
#pragma unroll
        for (int mt = 0; mt < 2; mt++)
#pragma unroll
            for (int nt = 0; nt < 4; nt++) {
                int rA = m0 + mt * 16 + (lane >> 2);
                int rB = rA + 8;
                int c = n0 + nt * 8 + 2 * (lane & 3);
                float b0 = smb2[c], b1 = smb2[c + 1];
                float wA = swt[rA], wB = swt[rB];
                int eA = e0 + rA, eB = e0 + rB;
                if (eA < NE) {
                    float2 v;
                    v.x = (acc2[mt][nt][0] + b0) * wA;
                    v.y = (acc2[mt][nt][1] + b1) * wA;
                    stcs_f2(&g_msgbuf[(u64)eA * 128 + c], v);
                }
                if (eB < NE) {
                    float2 v;
                    v.x = (acc2[mt][nt][2] + b0) * wB;
                    v.y = (acc2[mt][nt][3] + b1) * wB;
                    stcs_f2(&g_msgbuf[(u64)eB * 128 + c], v);
                }
            }
        __syncthreads();
    }
}

// ---------------- node update: CSR gather + HMMA MLP + LN + fused pre ----------------
#define UPP 136
#define U_AH 0
#define U_AL 17408
#define U_WH 34816
#define U_WL 69632
#define SMEM_UPD 104448

__global__ void __launch_bounds__(256, 2)
k_update(const float* __restrict__ ub1,
         const float* __restrict__ ub2,
         const float* __restrict__ lng,
         const float* __restrict__ lnb, int layer, int do_pre) {
    extern __shared__ char sm[];
    u16* sAh = (u16*)(sm + U_AH);
    u16* sAl = (u16*)(sm + U_AL);
    u16* sWh = (u16*)(sm + U_WH);
    u16* sWl = (u16*)(sm + U_WL);
    float* stage = (float*)(sm + U_WH);
    u32 sb = smem_u32(sm);
    int tid = threadIdx.x, lane = tid & 31, w = tid >> 5;
    int n0 = blockIdx.x * 64;

    // phase 0: CSR gather of weighted messages (agg in registers, streaming loads)
    int ln = tid >> 2, q = tid & 3;
    int nn = n0 + ln;
    float agg[32];
#pragma unroll
    for (int t = 0; t < 32; t++) agg[t] = 0.f;
    if (nn < NN) {
        int j0 = g_row[nn], j1 = g_cur[nn];
        for (int j = j0; j < j1; j++) {
            int e = g_eord[j];
            const float* mp = &g_msgbuf[(u64)e * 128 + q * 32];
#pragma unroll
            for (int t = 0; t < 8; t++) {
                float4 v = ldcs_f4(&mp[t * 4]);
                agg[t * 4]     += v.x;
                agg[t * 4 + 1] += v.y;
                agg[t * 4 + 2] += v.z;
                agg[t * 4 + 3] += v.w;
            }
        }
    }

    // A1 = h split
    for (int idx = tid; idx < 64 * 16; idx += 256) {
        int r = idx >> 4, c = (idx & 15) * 8;
        int n = n0 + r;
        if (n < NN) {
            *(uint4*)&sAh[r * UPP + c] = *(const uint4*)&g_hh[n * HID + c];
            *(uint4*)&sAl[r * UPP + c] = *(const uint4*)&g_hl[n * HID + c];
        } else {
            uint4 z = make_uint4(0, 0, 0, 0);
            *(uint4*)&sAh[r * UPP + c] = z;
            *(uint4*)&sAl[r * UPP + c] = z;
        }
    }
    // Wa (uw1 in-half 0)
    {
        const u16* wh = g_U1h + layer * 32768;
        const u16* wl = g_U1l + layer * 32768;
        for (int idx = tid; idx < 128 * 16; idx += 256) {
            int r = idx >> 4, c = (idx & 15) * 8;
            *(uint4*)&sWh[r * UPP + c] = *(const uint4*)&wh[r * 128 + c];
            *(uint4*)&sWl[r * UPP + c] = *(const uint4*)&wl[r * 128 + c];
        }
    }
    __syncthreads();

    int m0 = (w & 1) * 32, nw0 = (w >> 1) * 32;
    float acc[2][4][4];
#pragma unroll
    for (int i = 0; i < 2; i++)
#pragma unroll
        for (int j = 0; j < 4; j++)
#pragma unroll
            for (int k = 0; k < 4; k++) acc[i][j][k] = 0.f;

    for (int ks = 0; ks < 8; ks++) {
        int kb = ks * 16;
        u32 ah[2][4], al[2][4];
#pragma unroll
        for (int mt = 0; mt < 2; mt++) {
            int r = m0 + mt * 16 + (lane & 15);
            int c = kb + ((lane >> 4) << 3);
            u32 off = (u32)(r * UPP + c) * 2;
            ldsm4(ah[mt], sb + U_AH + off);
            ldsm4(al[mt], sb + U_AL + off);
        }
#pragma unroll
        for (int nt = 0; nt < 4; nt++) {
            int rn = nw0 + nt * 8 + (lane & 7);
            int cn = kb + (((lane >> 3) & 1) << 3);
            u32 offb = (u32)(rn * UPP + cn) * 2;
            u32 bh[2], bl[2];
            ldsm2(bh, sb + U_WH + offb);
            ldsm2(bl, sb + U_WL + offb);
#pragma unroll
            for (int mt = 0; mt < 2; mt++) {
                mma16816(acc[mt][nt], ah[mt], bh);
                mma16816(acc[mt][nt], ah[mt], bl);
                mma16816(acc[mt][nt], al[mt], bh);
            }
        }
    }
    __syncthreads();

    // A2 = agg split; Wb (uw1 in-half 1)
    {
#pragma unroll
        for (int t = 0; t < 16; t++) {
            u32 h, l;
            split2(agg[2 * t], agg[2 * t + 1], h, l);
            *(u32*)&sAh[ln * UPP + q * 32 + 2 * t] = h;
            *(u32*)&sAl[ln * UPP + q * 32 + 2 * t] = l;
        }
        const u16* wh = g_U1h + layer * 32768 + 16384;
        const u16* wl = g_U1l + layer * 32768 + 16384;
        for (int idx = tid; idx < 128 * 16; idx += 256) {
            int r = idx >> 4, c = (idx & 15) * 8;
            *(uint4*)&sWh[r * UPP + c] = *(const uint4*)&wh[r * 128 + c];
            *(uint4*)&sWl[r * UPP + c] = *(const uint4*)&wl[r * 128 + c];
        }
    }
    __syncthreads();

    for (int ks = 0; ks < 8; ks++) {
        int kb = ks * 16;
        u32 ah[2][4], al[2][4];
#pragma unroll
        for (int mt = 0; mt < 2; mt++) {
            int r = m0 + mt * 16 + (lane & 15);
            int c = kb + ((lane >> 4) << 3);
            u32 off = (u32)(r * UPP + c) * 2;
            ldsm4(ah[mt], sb + U_AH + off);
            ldsm4(al[mt], sb + U_AL + off);
        }
#pragma unroll
        for (int nt = 0; nt < 4; nt++) {
            int rn = nw0 + nt * 8 + (lane & 7);
            int cn = kb + (((lane >> 3) & 1) << 3);
            u32 offb = (u32)(rn * UPP + cn) * 2;
            u32 bh[2], bl[2];
            ldsm2(bh, sb + U_WH + offb);
            ldsm2(bl, sb + U_WL + offb);
#pragma unroll
            for (int mt = 0; mt < 2; mt++) {
                mma16816(acc[mt][nt], ah[mt], bh);
                mma16816(acc[mt][nt], ah[mt], bl);
                mma16816(acc[mt][nt], al[mt], bh);
            }
        }
    }
    __syncthreads();

    // relu(acc + ub1) -> re-split into A tiles
#pragma unroll
    for (int mt = 0; mt < 2; mt++)
#pragma unroll
        for (int nt = 0; nt < 4; nt++) {
            int rA = m0 + mt * 16 + (lane >> 2);
            int rB = rA + 8;
            int c = nw0 + nt * 8 + 2 * (lane & 3);
            float b0 = ub1[c], b1 = ub1[c + 1];
            u32 h, l;
            split2(fmaxf(acc[mt][nt][0] + b0, 0.f),
                   fmaxf(acc[mt][nt][1] + b1, 0.f), h, l);
            *(u32*)&sAh[rA * UPP + c] = h;
            *(u32*)&sAl[rA * UPP + c] = l;
            split2(fmaxf(acc[mt][nt][2] + b0, 0.f),
                   fmaxf(acc[mt][nt][3] + b1, 0.f), h, l);
            *(u32*)&sAh[rB * UPP + c] = h;
            *(u32*)&sAl[rB * UPP + c] = l;
        }
    // W2 = uw2 split
    {
        const u16* wh = g_U2h + layer * 128 * 128;
        const u16* wl = g_U2l + layer * 128 * 128;
        for (int idx = tid; idx < 128 * 16; idx += 256) {
            int r = idx >> 4, c = (idx & 15) * 8;
            *(uint4*)&sWh[r * UPP + c] = *(const uint4*)&wh[r * 128 + c];
            *(uint4*)&sWl[r * UPP + c] = *(const uint4*)&wl[r * 128 + c];
        }
    }
    __syncthreads();

    float acc2[2][4][4];
#pragma unroll
    for (int i = 0; i < 2; i++)
#pragma unroll
        for (int j = 0; j < 4; j++)
#pragma unroll
            for (int k = 0; k < 4; k++) acc2[i][j][k] = 0.f;

    for (int ks = 0; ks < 8; ks++) {
        int kb = ks * 16;
        u32 ah[2][4], al[2][4];
#pragma unroll
        for (int mt = 0; mt < 2; mt++) {
            int r = m0 + mt * 16 + (lane & 15);
            int c = kb + ((lane >> 4) << 3);
            u32 off = (u32)(r * UPP + c) * 2;
            ldsm4(ah[mt], sb + U_AH + off);
            ldsm4(al[mt], sb + U_AL + off);
        }
#pragma unroll
        for (int nt = 0; nt < 4; nt++) {
            int rn = nw0 + nt * 8 + (lane & 7);
            int cn = kb + (((lane >> 3) & 1) << 3);
            u32 offb = (u32)(rn * UPP + cn) * 2;
            u32 bh[2], bl[2];
            ldsm2(bh, sb + U_WH + offb);
            ldsm2(bl, sb + U_WL + offb);
#pragma unroll
            for (int mt = 0; mt < 2; mt++) {
                mma16816(acc2[mt][nt], ah[mt], bh);
                mma16816(acc2[mt][nt], ah[mt], bl);
                mma16816(acc2[mt][nt], al[mt], bh);
            }
        }
    }
    __syncthreads();  // W tiles dead -> stage

#pragma unroll
    for (int mt = 0; mt < 2; mt++)
#pragma unroll
        for (int nt = 0; nt < 4; nt++) {
            int rA = m0 + mt * 16 + (lane >> 2);
            int rB = rA + 8;
            int c = nw0 + nt * 8 + 2 * (lane & 3);
            stage[rA * 132 + c]     = acc2[mt][nt][0];
            stage[rA * 132 + c + 1] = acc2[mt][nt][1];
            stage[rB * 132 + c]     = acc2[mt][nt][2];
            stage[rB * 132 + c + 1] = acc2[mt][nt][3];
        }
    __syncthreads();

    // LN: 4 threads per row (ln, q); also deposit split h into A tiles for fused pre
    {
        int c0 = q * 32;
        float v[32];
        float s = 0.f, sq = 0.f;
        if (nn < NN) {
#pragma unroll
            for (int t4 = 0; t4 < 8; t4++) {
                float4 hres = *(const float4*)&g_h[nn * HID + c0 + t4 * 4];
                float hr[4] = {hres.x, hres.y, hres.z, hres.w};
#pragma unroll
                for (int j = 0; j < 4; j++) {
                    int t = t4 * 4 + j;
                    float val = stage[ln * 132 + c0 + t] + ub2[c0 + t] + hr[j];
                    val = fmaxf(val, 0.f);
                    v[t] = val;
                    s += val;
                    sq += val * val;
                }
            }
        } else {
#pragma unroll
            for (int t = 0; t < 32; t++) v[t] = 0.f;
        }
        s  += __shfl_xor_sync(0xffffffffu, s, 1);
        s  += __shfl_xor_sync(0xffffffffu, s, 2);
        sq += __shfl_xor_sync(0xffffffffu, sq, 1);
        sq += __shfl_xor_sync(0xffffffffu, sq, 2);
        float mu = s * (1.f / 128.f);
        float var = sq * (1.f / 128.f) - mu * mu;
        float rs = rsqrtf(var + 1e-5f);
        float o[32];
#pragma unroll
        for (int t = 0; t < 32; t++)
            o[t] = (v[t] - mu) * rs * lng[c0 + t] + lnb[c0 + t];
        if (nn < NN) {
#pragma unroll
            for (int t4 = 0; t4 < 8; t4++) {
                *(float4*)&g_h[nn * HID + c0 + t4 * 4] =
                    make_float4(o[t4 * 4], o[t4 * 4 + 1], o[t4 * 4 + 2], o[t4 * 4 + 3]);
                u32 h0, l0, h1, l1;
                split2(o[t4 * 4], o[t4 * 4 + 1], h0, l0);
                split2(o[t4 * 4 + 2], o[t4 * 4 + 3], h1, l1);
                *(u32*)&g_hh[nn * HID + c0 + t4 * 4]     = h0;
                *(u32*)&g_hh[nn * HID + c0 + t4 * 4 + 2] = h1;
                *(u32*)&g_hl[nn * HID + c0 + t4 * 4]     = l0;
                *(u32*)&g_hl[nn * HID + c0 + t4 * 4 + 2] = l1;
            }
        }
        if (do_pre) {
#pragma unroll
            for (int t = 0; t < 16; t++) {
                u32 h, l;
                split2(o[2 * t], o[2 * t + 1], h, l);
                *(u32*)&sAh[ln * UPP + c0 + 2 * t] = h;
                *(u32*)&sAl[ln * UPP + c0 + 2 * t] = l;
            }
        }
    }

    // ---- fused next-layer node_pre ----
    if (do_pre) {
        __syncthreads();
        int npl = layer + 1;
        for (int half = 0; half < 2; half++) {
            const u16* wh = g_NPh + npl * 256 * 128 + half * 128 * 128;
            const u16* wl = g_NPl + npl * 256 * 128 + half * 128 * 128;
            for (int idx = tid; idx < 128 * 16; idx += 256) {
                int r = idx >> 4, c = (idx & 15) * 8;
                *(uint4*)&sWh[r * UPP + c] = *(const uint4*)&wh[r * 128 + c];
                *(uint4*)&sWl[r * UPP + c] = *(const uint4*)&wl[r * 128 + c];
            }
            __syncthreads();
            float accp[2][4][4];
#pragma unroll
            for (int i = 0; i < 2; i++)
#pragma unroll
                for (int j = 0; j < 4; j++)
#pragma unroll
                    for (int k = 0; k < 4; k++) accp[i][j][k] = 0.f;
            for (int ks = 0; ks < 8; ks++) {
                int kb = ks * 16;
                u32 ah[2][4], al[2][4];
#pragma unroll
                for (int mt = 0; mt < 2; mt++) {
                    int r = m0 + mt * 16 + (lane & 15);
                    int c = kb + ((lane >> 4) << 3);
                    u32 off = (u32)(r * UPP + c) * 2;
                    ldsm4(ah[mt], sb + U_AH + off);
                    ldsm4(al[mt], sb + U_AL + off);
                }
#pragma unroll
                for (int nt = 0; nt < 4; nt++) {
                    int rn = nw0 + nt * 8 + (lane & 7);
                    int cn = kb + (((lane >> 3) & 1) << 3);
                    u32 offb = (u32)(rn * UPP + cn) * 2;
                    u32 bh[2], bl[2];
                    ldsm2(bh, sb + U_WH + offb);
                    ldsm2(bl, sb + U_WL + offb);
#pragma unroll
                    for (int mt = 0; mt < 2; mt++) {
                        mma16816(accp[mt][nt], ah[mt], bh);
                        mma16816(accp[mt][nt], ah[mt], bl);
                        mma16816(accp[mt][nt], al[mt], bh);
                    }
                }
            }
#pragma unroll
            for (int mt = 0; mt < 2; mt++)
#pragma unroll
                for (int nt = 0; nt < 4; nt++) {
                    int rA = m0 + mt * 16 + (lane >> 2);
                    int rB = rA + 8;
                    int c = half * 128 + nw0 + nt * 8 + 2 * (lane & 3);
                    int nA = n0 + rA, nB = n0 + rB;
                    if (nA < NN) {
                        g_pre[(u64)nA * 256 + c]     = accp[mt][nt][0];
                        g_pre[(u64)nA * 256 + c + 1] = accp[mt][nt][1];
                    }
                    if (nB < NN) {
                        g_pre[(u64)nB * 256 + c]     = accp[mt][nt][2];
                        g_pre[(u64)nB * 256 + c + 1] = accp[mt][nt][3];
                    }
                }
            __syncthreads();
        }
    }
}

// ---------------- final readout ----------------
__global__ void k_final(const float* __restrict__ gc,
                        const float* __restrict__ qw1,
                        const float* __restrict__ qb1,
                        const float* __restrict__ qw2,
                        const float* __restrict__ qb2p,
                        float* __restrict__ out) {
    __shared__ float sA[32 * 33];
    __shared__ float sW[128 * 33];
    __shared__ float sctx[64];
    __shared__ float sout[32];
    int tid = threadIdx.x;
    int n0 = blockIdx.x * 32;
    if (tid < 64) sctx[tid] = gc[tid];
    if (tid < 32) sout[tid] = qb2p[0];
    __syncthreads();
    int tc = tid & 31, trg = tid >> 5;
    float acc[4][4] = {};
    for (int kb = 0; kb < 192; kb += 32) {
        for (int idx = tid; idx < 32 * 32; idx += NT) {
            int r = idx >> 5, kk = idx & 31;
            int n = n0 + r;
            int kg = kb + kk;
            float v = 0.f;
            if (n < NN) v = (kg < 128) ? g_h[n * HID + kg] : sctx[kg - 128];
            sA[r * 33 + kk] = v;
        }
        for (int idx = tid; idx < 128 * 32; idx += NT) {
            int o = idx >> 5, kk = idx & 31;
            sW[o * 33 + kk] = qw1[o * 192 + kb + kk];
        }
        __syncthreads();
#pragma unroll 8
        for (int k = 0; k < 32; k++) {
            float a[4], w[4];
#pragma unroll
            for (int i = 0; i < 4; i++) a[i] = sA[(trg * 4 + i) * 33 + k];
#pragma unroll
            for (int j = 0; j < 4; j++) w[j] = sW[(tc + 32 * j) * 33 + k];
#pragma unroll
            for (int i = 0; i < 4; i++)
#pragma unroll
                for (int j = 0; j < 4; j++) acc[i][j] += a[i] * w[j];
        }
        __syncthreads();
    }
    float p[4] = {0.f, 0.f, 0.f, 0.f};
#pragma unroll
    for (int j = 0; j < 4; j++) {
        int c = tc + 32 * j;
        float b = qb1[c], w2 = qw2[c];
#pragma unroll
        for (int i = 0; i < 4; i++) {
            float v = fmaxf(acc[i][j] + b, 0.f);
            p[i] += v * w2;
        }
    }
#pragma unroll
    for (int i = 0; i < 4; i++) atomicAdd(&sout[trg * 4 + i], p[i]);
    __syncthreads();
    if (tid < 32) {
        int n = n0 + tid;
        if (n < NN) out[n] = sout[tid];
    }
}

// ---------------- launch ----------------
extern "C" void kernel_launch(void* const* d_in, const int* in_sizes, int n_in,
                              void* d_out, int out_size) {
    const float* x    = (const float*)d_in[0];
    const void*  eidx = d_in[1];
    const float* ea   = (const float*)d_in[2];
    const float* gc   = (const float*)d_in[3];
    const float* npw  = (const float*)d_in[4];
    const float* npb  = (const float*)d_in[5];
    const float* mw1  = (const float*)d_in[6];
    const float* mb1  = (const float*)d_in[7];
    const float* mw2  = (const float*)d_in[8];
    const float* mb2  = (const float*)d_in[9];
    const float* aw1  = (const float*)d_in[10];
    const float* ab1  = (const float*)d_in[11];
    const float* aw2  = (const float*)d_in[12];
    const float* ab2  = (const float*)d_in[13];
    const float* uw1  = (const float*)d_in[14];
    const float* ub1  = (const float*)d_in[15];
    const float* uw2  = (const float*)d_in[16];
    const float* ub2  = (const float*)d_in[17];
    const float* lng  = (const float*)d_in[18];
    const float* lnb  = (const float*)d_in[19];
    const float* qw1  = (const float*)d_in[20];
    const float* qb1  = (const float*)d_in[21];
    const float* qw2  = (const float*)d_in[22];
    const float* qb2  = (const float*)d_in[23];
    float* out = (float*)d_out;

    cudaFuncSetAttribute(k_msg, cudaFuncAttributeMaxDynamicSharedMemorySize, SMEM_MSG2);
    cudaFuncSetAttribute(k_node_pre, cudaFuncAttributeMaxDynamicSharedMemorySize, SMEM_NP);
    cudaFuncSetAttribute(k_update, cudaFuncAttributeMaxDynamicSharedMemorySize, SMEM_UPD);

    int prep_tot = 3 * (256 * 128 + 192 * 16 + 128 * 128 + 256 * 128 + 128 * 128);
    k_prep<<<(prep_tot + 255) / 256, 256>>>(mw1, mw2, aw1, uw1, uw2);
    k_detect<<<1, NT>>>((const unsigned*)eidx);
    k_convert<<<(NE + NT - 1) / NT, NT>>>(eidx, ea);
    k_hist<<<(NE + 255) / 256, 256>>>();
    k_scan<<<1, 1024>>>();
    k_scatter<<<(NE + 255) / 256, 256>>>();
    k_nodeproj<<<(NN + 31) / 32, NT>>>(x, npw, npb);

    int ngrid = (NN + 63) / 64;
    k_node_pre<<<ngrid, 256, SMEM_NP>>>(0);
    for (int l = 0; l < 3; l++) {
        k_attn_lite<<<(NE + 63) / 64, 256>>>(ea, aw1 + l * 64 * 272, ab1 + l * 64,
                                             aw2 + l * 64, ab2 + l, l);
        k_exp<<<(NE + NT - 1) / NT, NT>>>(l);
        k_msg<<<MSG_GRID, 256, SMEM_MSG2>>>(mb1 + l * 128, mb2 + l * 128, l);
        k_update<<<ngrid, 256, SMEM_UPD>>>(ub1 + l * 128, ub2 + l * 128,
                                           lng + l * 128, lnb + l * 128, l,
                                           (l < 2) ? 1 : 0);
    }
    k_final<<<(NN + 31) / 32, NT>>>(gc, qw1, qb1, qw2, qb2, out);
}